// round 12
// baseline (speedup 1.0000x reference)
#include <cuda_runtime.h>
#include <cuda_fp16.h>
#include <cstdint>
#include <cstddef>

// Problem dims
#define NL   6
#define TT   128
#define NB   256
#define ND   512
#define NH   8
#define NDFF 2048
#define NSUB 64
#define NTOK (TT * NB)   // 32768 tokens
// All activation buffers use row index p = t*NB + b ("natural" [T,B,D] order).

// mma.sync GEMM tile config (fp16 in, fp32 accum)
#define BM 128
#define BN 128
#define BKH 64                         // 64 halves = 128B row
#define NSTAGE 3
#define A_BYTES (BM * BKH * 2)         // 16384
#define STAGE_BYTES (2 * A_BYTES)      // 32768
#define DYN_SMEM (NSTAGE * STAGE_BYTES)  // 98304

// ---------------------------------------------------------------------------
// Scratch (__device__ globals; no allocation allowed)
// ---------------------------------------------------------------------------
__device__ __align__(16) __half g_s_h [(size_t)NL * NTOK * ND];  // all layers
__device__ __align__(16) __half g_t_h [(size_t)NTOK * ND];
__device__ __align__(16) float  g_scores[(size_t)NL * NH * TT * NB];
__device__ __align__(16) __half g_wm_h[(size_t)NTOK * ND];
__device__ __align__(16) float  g_agg [(size_t)NTOK * ND];   // holds src + agg
__device__ __align__(16) __half g_x_h [(size_t)NTOK * ND];
__device__ __align__(16) __half g_h1_h[(size_t)NTOK * NDFF];
__device__ __align__(16) float  g_y   [(size_t)NTOK * ND];   // holds x + y
__device__ __align__(16) __half g_src_h[(size_t)NTOK * ND];
__device__ __align__(16) __half g_srcc_h[(size_t)NTOK * ND];
__device__ __align__(16) __half g_src0_h[(size_t)NTOK * ND];
// fp16 weights
__device__ __align__(16) __half g_wsp_h[(size_t)NL * ND * ND];
__device__ __align__(16) __half g_wtp_h[(size_t)NL * ND * ND];
__device__ __align__(16) __half g_wag_h[(size_t)NL * ND * ND];
__device__ __align__(16) __half g_wl1_h[(size_t)NL * NDFF * ND];
__device__ __align__(16) __half g_wl2_h[(size_t)NL * ND * NDFF];
__device__ __align__(16) __half g_wmg_h[(size_t)NL * NH * NSUB * NSUB];

// ---------------------------------------------------------------------------
// PTX helpers (baseline sm_80+ instructions only)
// ---------------------------------------------------------------------------
__device__ __forceinline__ uint32_t smem_u32(const void* p) {
    uint32_t a;
    asm("{ .reg .u64 t; cvta.to.shared.u64 t, %1; cvt.u32.u64 %0, t; }"
        : "=r"(a) : "l"(p));
    return a;
}
__device__ __forceinline__ void cp_async16(uint32_t dst, const void* src) {
    asm volatile("cp.async.cg.shared.global [%0], [%1], 16;" :: "r"(dst), "l"(src));
}
#define CP_COMMIT() asm volatile("cp.async.commit_group;" ::: "memory")
#define CP_WAIT1()  asm volatile("cp.async.wait_group 1;" ::: "memory")
#define CP_WAIT0()  asm volatile("cp.async.wait_group 0;" ::: "memory")

__device__ __forceinline__ void ldsm_x4(uint32_t* r, uint32_t addr) {
    asm volatile("ldmatrix.sync.aligned.m8n8.x4.shared.b16 {%0,%1,%2,%3}, [%4];"
                 : "=r"(r[0]), "=r"(r[1]), "=r"(r[2]), "=r"(r[3]) : "r"(addr));
}
__device__ __forceinline__ void mma16816(float* d, const uint32_t* a,
                                         uint32_t b0, uint32_t b1) {
    asm volatile(
        "mma.sync.aligned.m16n8k16.row.col.f32.f16.f16.f32 "
        "{%0,%1,%2,%3}, {%4,%5,%6,%7}, {%8,%9}, {%0,%1,%2,%3};"
        : "+f"(d[0]), "+f"(d[1]), "+f"(d[2]), "+f"(d[3])
        : "r"(a[0]), "r"(a[1]), "r"(a[2]), "r"(a[3]), "r"(b0), "r"(b1));
}

// ---------------------------------------------------------------------------
// cooperative stage loader (128 threads): A + B tile [128 x 64h], swizzled
// ---------------------------------------------------------------------------
__device__ __forceinline__ void load_stage(const __half* __restrict__ Ag,
                                           const __half* __restrict__ Wg,
                                           int K, uint32_t abase, uint32_t bbase,
                                           int tid) {
    #pragma unroll
    for (int it = 0; it < 8; it++) {
        int q = tid + it * 128;        // 0..1023 16B chunks per operand
        int r = q >> 3;                // row 0..127
        int c = q & 7;                 // logical 16B chunk in row
        uint32_t off = (uint32_t)(r * 128 + ((c ^ (r & 7)) << 4));
        cp_async16(abase + off, Ag + (size_t)r * K + c * 8);
        cp_async16(bbase + off, Wg + (size_t)r * K + c * 8);
    }
    CP_COMMIT();
}

// fragment loader: one k16 slice for this warp (64x64 warp tile)
__device__ __forceinline__ void load_frags(uint32_t aB, uint32_t bB, int ks,
                                           int arow, int brow, int axor, int bxor,
                                           int csel,
                                           uint32_t af[4][4], uint32_t bf[4][4]) {
    #pragma unroll
    for (int mt = 0; mt < 4; mt++) {
        uint32_t addr = aB + (uint32_t)((arow + mt * 16) * 128)
                      + (uint32_t)((((ks << 1) + csel) ^ axor) << 4);
        ldsm_x4(af[mt], addr);
    }
    #pragma unroll
    for (int np = 0; np < 4; np++) {
        uint32_t addr = bB + (uint32_t)((brow + np * 16) * 128)
                      + (uint32_t)((((ks << 1) + csel) ^ bxor) << 4);
        ldsm_x4(bf[np], addr);
    }
}

// ---------------------------------------------------------------------------
// fp16 tensor-core GEMM: C[M,N] = A[M,K]@W[N,K]^T + bias (+residual), opt relu.
// KV (compile-time K) fully unrolls the main loop.
// ADDMODE: 0 none; 1 fp32 residual same layout; 3 fp16 residual same layout.
// SCORE:   0 none; 1 store s-part scores (BATCHED over layers via blockIdx.z);
//          2 atomicAdd t-part scores.
// grid (N/128, M/128[, NL when SCORE==1]), 128 threads (4 warps, 2x2).
// ---------------------------------------------------------------------------
template <int RELU, int OUTH, int ADDMODE, int SCORE, int KV>
__global__ __launch_bounds__(128, 2)
void tc_gemm(const __half* __restrict__ A, const __half* __restrict__ W,
             const float* __restrict__ bias, float* __restrict__ Cf,
             __half* __restrict__ Ch, const void* __restrict__ Res,
             const float* __restrict__ aw, float* __restrict__ sbuf,
             int N) {
    __shared__ float s_bias[BN];
    extern __shared__ __align__(1024) char dynsmem[];
    const uint32_t dynbase = smem_u32(dynsmem);
    constexpr int K = KV;
    constexpr int NCH = KV / BKH;

    if (SCORE == 1) {                  // batched over layers
        const int zl = blockIdx.z;
        W    += (size_t)zl * ND * ND;
        bias += zl * ND;
        Ch   += (size_t)zl * NTOK * ND;
        aw   += zl * NH * 2 * NSUB;
        sbuf += (size_t)zl * NH * TT * NB;
    }

    const int tid = threadIdx.x;
    const int wid = tid >> 5, lid = tid & 31;
    const int wm_ = wid >> 1, wn_ = wid & 1;
    const int m0 = blockIdx.y * BM, n0 = blockIdx.x * BN;

    s_bias[tid] = bias[n0 + tid];

    const __half* Abase = A + (size_t)m0 * K;
    const __half* Wbase = W + (size_t)n0 * K;

    const int sub = lid >> 3, wi = lid & 7;
    const int csel = sub >> 1;
    const int arow = wm_ * 64 + (sub & 1) * 8 + wi;
    const int brow = wn_ * 64 + (sub & 1) * 8 + wi;
    const int axor = arow & 7, bxor = brow & 7;

    #pragma unroll
    for (int c = 0; c < NSTAGE - 1; c++)
        load_stage(Abase + c * BKH, Wbase + c * BKH, K,
                   dynbase + c * STAGE_BYTES,
                   dynbase + c * STAGE_BYTES + A_BYTES, tid);

    float acc[4][8][4] = {};
    uint32_t afr[2][4][4], bfr[2][4][4];

    #pragma unroll
    for (int i = 0; i < NCH; i++) {
        const int stage = i % NSTAGE;
        CP_WAIT1();
        __syncthreads();
        const int j = i + NSTAGE - 1;
        if (j < NCH) {
            const int sj = j % NSTAGE;
            load_stage(Abase + j * BKH, Wbase + j * BKH, K,
                       dynbase + sj * STAGE_BYTES,
                       dynbase + sj * STAGE_BYTES + A_BYTES, tid);
        } else {
            CP_COMMIT();
        }

        const uint32_t aB = dynbase + stage * STAGE_BYTES;
        const uint32_t bB = aB + A_BYTES;

        load_frags(aB, bB, 0, arow, brow, axor, bxor, csel, afr[0], bfr[0]);
        #pragma unroll
        for (int ks = 0; ks < 4; ks++) {
            int cur = ks & 1;
            if (ks < 3)
                load_frags(aB, bB, ks + 1, arow, brow, axor, bxor, csel,
                           afr[cur ^ 1], bfr[cur ^ 1]);
            #pragma unroll
            for (int mt = 0; mt < 4; mt++)
                #pragma unroll
                for (int nt = 0; nt < 8; nt++)
                    mma16816(acc[mt][nt], afr[cur][mt],
                             bfr[cur][nt >> 1][nt & 1],
                             bfr[cur][nt >> 1][(nt & 1) + 2]);
        }
    }

    float waw[16];
    const int shead = (n0 >> 6) + wn_;
    if (SCORE) {
        const int off = (SCORE == 2) ? 64 : 0;
        #pragma unroll
        for (int nt = 0; nt < 8; nt++) {
            int u = nt * 8 + (lid & 3) * 2;
            waw[nt * 2]     = __ldg(aw + shead * 128 + off + u);
            waw[nt * 2 + 1] = __ldg(aw + shead * 128 + off + u + 1);
        }
    }

    #pragma unroll
    for (int mt = 0; mt < 4; mt++) {
        int row = m0 + wm_ * 64 + mt * 16 + (lid >> 2);
        size_t rb0 = (size_t)row * N;
        size_t rb1 = (size_t)(row + 8) * N;
        float sc0 = 0.f, sc1 = 0.f;
        #pragma unroll
        for (int nt = 0; nt < 8; nt++) {
            int coll = wn_ * 64 + nt * 8 + (lid & 3) * 2;
            int col = n0 + coll;
            float bx = s_bias[coll], by = s_bias[coll + 1];
            float v0 = acc[mt][nt][0] + bx, v1 = acc[mt][nt][1] + by;
            float v2 = acc[mt][nt][2] + bx, v3 = acc[mt][nt][3] + by;
            if (ADDMODE == 1) {
                const float* Rf = (const float*)Res;
                float2 r0 = *(const float2*)(Rf + rb0 + col);
                float2 r1 = *(const float2*)(Rf + rb1 + col);
                v0 += r0.x; v1 += r0.y; v2 += r1.x; v3 += r1.y;
            } else if (ADDMODE == 3) {
                const __half* Rh = (const __half*)Res;
                float2 r0 = __half22float2(*(const __half2*)(Rh + rb0 + col));
                float2 r1 = __half22float2(*(const __half2*)(Rh + rb1 + col));
                v0 += r0.x; v1 += r0.y; v2 += r1.x; v3 += r1.y;
            }
            if (RELU) {
                v0 = fmaxf(v0, 0.f); v1 = fmaxf(v1, 0.f);
                v2 = fmaxf(v2, 0.f); v3 = fmaxf(v3, 0.f);
            }
            if (SCORE) {
                sc0 += v0 * waw[nt * 2] + v1 * waw[nt * 2 + 1];
                sc1 += v2 * waw[nt * 2] + v3 * waw[nt * 2 + 1];
            }
            if (OUTH) {
                *(__half2*)(Ch + (size_t)row * N + col)       = __floats2half2_rn(v0, v1);
                *(__half2*)(Ch + (size_t)(row + 8) * N + col) = __floats2half2_rn(v2, v3);
            } else {
                *(float2*)(Cf + (size_t)row * N + col)       = make_float2(v0, v1);
                *(float2*)(Cf + (size_t)(row + 8) * N + col) = make_float2(v2, v3);
            }
        }
        if (SCORE) {
            sc0 += __shfl_xor_sync(0xffffffffu, sc0, 1);
            sc0 += __shfl_xor_sync(0xffffffffu, sc0, 2);
            sc1 += __shfl_xor_sync(0xffffffffu, sc1, 1);
            sc1 += __shfl_xor_sync(0xffffffffu, sc1, 2);
            if ((lid & 3) == 0) {
                int tok0 = row, tok1 = row + 8;        // tok = t*NB + b
                int t0_ = tok0 >> 8, b0_ = tok0 & 255;
                int t1_ = tok1 >> 8, b1_ = tok1 & 255;
                float* sp0 = sbuf + (shead * TT + t0_) * NB + b0_;
                float* sp1 = sbuf + (shead * TT + t1_) * NB + b1_;
                if (SCORE == 1) { *sp0 = sc0; *sp1 = sc1; }
                else           { atomicAdd(sp0, sc0); atomicAdd(sp1, sc1); }
            }
        }
    }
}

// ---------------------------------------------------------------------------
// msg tensor-core kernel with FUSED softmax: per (head, 128 tokens) block.
// ---------------------------------------------------------------------------
__global__ __launch_bounds__(128)
void msg_mma_kernel(const __half* __restrict__ mwh,
                    const float* __restrict__ mb,
                    const __half* __restrict__ s_h,
                    const float* __restrict__ sbuf) {
    __shared__ __align__(16) __half prodS[128 * 64];
    __shared__ __align__(16) __half mwS[64 * 64];
    __shared__ float wtsS[128];
    __shared__ float mbS[64];
    __shared__ float redm[4], reds[4];

    const int h  = blockIdx.y;
    const int p0 = blockIdx.x * 128;
    const int tid = threadIdx.x;
    const int wid = tid >> 5, lid = tid & 31;

    if (tid < 64) mbS[tid] = mb[h * 64 + tid];

    {   // mw tile via cp.async (64 rows x 128B, swizzled)
        uint32_t base = smem_u32(mwS);
        #pragma unroll
        for (int it = 0; it < 4; it++) {
            int q = tid + it * 128;
            int r = q >> 3, c = q & 7;
            uint32_t off = (uint32_t)(r * 128 + ((c ^ (r & 7)) << 4));
            cp_async16(base + off, mwh + (size_t)(h * 64 + r) * 64 + c * 8);
        }
        CP_COMMIT();
    }

    {   // fused softmax over the 256-score row (h, t); t = p0/256
        const int t = p0 >> 8;
        const int boff = p0 & 255;               // 0 or 128
        const float* srow = sbuf + ((size_t)h * TT + t) * NB;
        float v0 = srow[tid];
        float v1 = srow[tid + 128];
        float mx = fmaxf(v0, v1);
        #pragma unroll
        for (int o = 16; o; o >>= 1) mx = fmaxf(mx, __shfl_xor_sync(0xffffffffu, mx, o));
        if (lid == 0) redm[wid] = mx;
        __syncthreads();
        mx = fmaxf(fmaxf(redm[0], redm[1]), fmaxf(redm[2], redm[3]));
        float e0 = __expf(v0 - mx), e1 = __expf(v1 - mx);
        float ss = e0 + e1;
        #pragma unroll
        for (int o = 16; o; o >>= 1) ss += __shfl_xor_sync(0xffffffffu, ss, o);
        if (lid == 0) reds[wid] = ss;
        __syncthreads();
        ss = (reds[0] + reds[1]) + (reds[2] + reds[3]);
        wtsS[tid] = ((boff == 0) ? e0 : e1) / ss;
    }

    {   // prod tile: s*t on load (coalesced 16B), swizzled store
        #pragma unroll
        for (int it = 0; it < 8; it++) {
            int q = tid + it * 128;
            int r = q >> 3, c = q & 7;
            size_t gidx = (size_t)(p0 + r) * ND + h * NSUB + c * 8;
            uint4 sr = *(const uint4*)(s_h + gidx);
            uint4 tr = *(const uint4*)(g_t_h + gidx);
            __half2 a0 = __hmul2(*(__half2*)&sr.x, *(__half2*)&tr.x);
            __half2 a1 = __hmul2(*(__half2*)&sr.y, *(__half2*)&tr.y);
            __half2 a2 = __hmul2(*(__half2*)&sr.z, *(__half2*)&tr.z);
            __half2 a3 = __hmul2(*(__half2*)&sr.w, *(__half2*)&tr.w);
            uint4 p4;
            p4.x = *(uint32_t*)&a0; p4.y = *(uint32_t*)&a1;
            p4.z = *(uint32_t*)&a2; p4.w = *(uint32_t*)&a3;
            uint32_t off = (uint32_t)(r * 128 + ((c ^ (r & 7)) << 4));
            *(uint4*)((char*)prodS + off) = p4;
        }
    }
    CP_WAIT0();
    __syncthreads();

    const int sub = lid >> 3, wi = lid & 7;
    const int csel = sub >> 1;
    const int arow = wid * 32 + (sub & 1) * 8 + wi;
    const int brow = (sub & 1) * 8 + wi;
    const int axor = arow & 7, bxor = brow & 7;
    const uint32_t aB = smem_u32(prodS), bB = smem_u32(mwS);

    float acc[2][8][4] = {};
    #pragma unroll
    for (int ks = 0; ks < 4; ks++) {
        uint32_t af[2][4], bf[4][4];
        #pragma unroll
        for (int mt = 0; mt < 2; mt++)
            ldsm_x4(af[mt], aB + (uint32_t)((arow + mt * 16) * 128)
                               + (uint32_t)((((ks << 1) + csel) ^ axor) << 4));
        #pragma unroll
        for (int np = 0; np < 4; np++)
            ldsm_x4(bf[np], bB + (uint32_t)((brow + np * 16) * 128)
                               + (uint32_t)((((ks << 1) + csel) ^ bxor) << 4));
        #pragma unroll
        for (int mt = 0; mt < 2; mt++)
            #pragma unroll
            for (int nt = 0; nt < 8; nt++)
                mma16816(acc[mt][nt], af[mt],
                         bf[nt >> 1][nt & 1], bf[nt >> 1][(nt & 1) + 2]);
    }

    #pragma unroll
    for (int mt = 0; mt < 2; mt++) {
        int rowl = wid * 32 + mt * 16 + (lid >> 2);
        float wt0 = wtsS[rowl], wt1 = wtsS[rowl + 8];
        size_t ob0 = (size_t)(p0 + rowl) * ND + h * NSUB;
        size_t ob1 = (size_t)(p0 + rowl + 8) * ND + h * NSUB;
        #pragma unroll
        for (int nt = 0; nt < 8; nt++) {
            int u = nt * 8 + (lid & 3) * 2;
            float m0 = acc[mt][nt][0] + mbS[u], m1 = acc[mt][nt][1] + mbS[u + 1];
            float m2 = acc[mt][nt][2] + mbS[u], m3 = acc[mt][nt][3] + mbS[u + 1];
            float v0 = fmaxf(wt0 * m0, 0.f), v1 = fmaxf(wt0 * m1, 0.f);
            float v2 = fmaxf(wt1 * m2, 0.f), v3 = fmaxf(wt1 * m3, 0.f);
            *(__half2*)(g_wm_h + ob0 + u) = __floats2half2_rn(v0, v1);
            *(__half2*)(g_wm_h + ob1 + u) = __floats2half2_rn(v2, v3);
        }
    }
}

// ---------------------------------------------------------------------------
__global__ __launch_bounds__(256)
void f32_to_f16_kernel(const float4* __restrict__ in, __half2* __restrict__ out, int n4) {
    for (int i = blockIdx.x * 256 + threadIdx.x; i < n4; i += gridDim.x * 256) {
        float4 v = in[i];
        out[2 * i]     = __floats2half2_rn(v.x, v.y);
        out[2 * i + 1] = __floats2half2_rn(v.z, v.w);
    }
}

// ---------------------------------------------------------------------------
// Warp-per-token LayerNorms. 8 warps/block. Rows p (layout-agnostic).
// ---------------------------------------------------------------------------
__global__ __launch_bounds__(256)
void ln1_kernel(const float* __restrict__ gam, const float* __restrict__ bet) {
    const int tok = blockIdx.x * 8 + (threadIdx.x >> 5);
    const int l = threadIdx.x & 31;
    const float4* a = (const float4*)(g_agg + (size_t)tok * ND);
    float4 v[4];
    float s = 0.f;
    #pragma unroll
    for (int k = 0; k < 4; k++) {
        v[k] = a[l + 32 * k];
        s += (v[k].x + v[k].y) + (v[k].z + v[k].w);
    }
    #pragma unroll
    for (int o = 16; o; o >>= 1) s += __shfl_xor_sync(0xffffffffu, s, o);
    const float mean = s * (1.0f / ND);
    float q = 0.f;
    #pragma unroll
    for (int k = 0; k < 4; k++) {
        v[k].x -= mean; v[k].y -= mean; v[k].z -= mean; v[k].w -= mean;
        q += (v[k].x * v[k].x + v[k].y * v[k].y) + (v[k].z * v[k].z + v[k].w * v[k].w);
    }
    #pragma unroll
    for (int o = 16; o; o >>= 1) q += __shfl_xor_sync(0xffffffffu, q, o);
    const float rstd = rsqrtf(q * (1.0f / ND) + 1e-5f);
    uint2* xr = (uint2*)(g_x_h + (size_t)tok * ND);
    #pragma unroll
    for (int k = 0; k < 4; k++) {
        int idx = l + 32 * k;
        float4 gg = *(const float4*)(gam + idx * 4);
        float4 bb = *(const float4*)(bet + idx * 4);
        __half2 h0 = __floats2half2_rn(v[k].x * rstd * gg.x + bb.x,
                                       v[k].y * rstd * gg.y + bb.y);
        __half2 h1 = __floats2half2_rn(v[k].z * rstd * gg.z + bb.z,
                                       v[k].w * rstd * gg.w + bb.w);
        uint2 u; u.x = *(uint32_t*)&h0; u.y = *(uint32_t*)&h1;
        xr[idx] = u;
    }
}

__global__ __launch_bounds__(256)
void ln2_kernel(const float* __restrict__ gam, const float* __restrict__ bet,
                float* __restrict__ out, int mode) {
    const int p = blockIdx.x * 8 + (threadIdx.x >> 5);
    const int l = threadIdx.x & 31;
    const float4* a = (const float4*)(g_y + (size_t)p * ND);
    float4 v[4];
    float s = 0.f;
    #pragma unroll
    for (int k = 0; k < 4; k++) {
        v[k] = a[l + 32 * k];
        s += (v[k].x + v[k].y) + (v[k].z + v[k].w);
    }
    #pragma unroll
    for (int o = 16; o; o >>= 1) s += __shfl_xor_sync(0xffffffffu, s, o);
    const float mean = s * (1.0f / ND);
    float q = 0.f;
    #pragma unroll
    for (int k = 0; k < 4; k++) {
        v[k].x -= mean; v[k].y -= mean; v[k].z -= mean; v[k].w -= mean;
        q += (v[k].x * v[k].x + v[k].y * v[k].y) + (v[k].z * v[k].z + v[k].w * v[k].w);
    }
    #pragma unroll
    for (int o = 16; o; o >>= 1) q += __shfl_xor_sync(0xffffffffu, q, o);
    const float rstd = rsqrtf(q * (1.0f / ND) + 1e-5f);
    const size_t obase = (size_t)p * ND;
    float4* orow = (float4*)(out + obase);
    uint2*  hrow = (uint2*)(g_src_h + obase);
    #pragma unroll
    for (int k = 0; k < 4; k++) {
        int idx = l + 32 * k;
        float4 gg = *(const float4*)(gam + idx * 4);
        float4 bb = *(const float4*)(bet + idx * 4);
        float4 o4;
        o4.x = v[k].x * rstd * gg.x + bb.x;
        o4.y = v[k].y * rstd * gg.y + bb.y;
        o4.z = v[k].z * rstd * gg.z + bb.z;
        o4.w = v[k].w * rstd * gg.w + bb.w;
        if (mode == 0) {
            orow[idx] = o4;
        } else {
            __half2 h0 = __floats2half2_rn(o4.x, o4.y);
            __half2 h1 = __floats2half2_rn(o4.z, o4.w);
            uint2 u; u.x = *(uint32_t*)&h0; u.y = *(uint32_t*)&h1;
            hrow[idx] = u;
        }
    }
}

// ---------------------------------------------------------------------------
extern "C" void kernel_launch(void* const* d_in, const int* in_sizes, int n_in,
                              void* d_out, int out_size) {
    const float* in_src  = (const float*)d_in[0];
    const float* in_srcc = (const float*)d_in[1];
    const float* w_sp = (const float*)d_in[2];
    const float* b_sp = (const float*)d_in[3];
    const float* w_tp = (const float*)d_in[4];
    const float* b_tp = (const float*)d_in[5];
    const float* w_at = (const float*)d_in[6];
    const float* w_mg = (const float*)d_in[8];
    const float* b_mg = (const float*)d_in[9];
    const float* w_ag = (const float*)d_in[10];
    const float* b_ag = (const float*)d_in[11];
    const float* w_l1 = (const float*)d_in[12];
    const float* b_l1 = (const float*)d_in[13];
    const float* w_l2 = (const float*)d_in[14];
    const float* b_l2 = (const float*)d_in[15];
    const float* g_n1 = (const float*)d_in[16];
    const float* bb_n1 = (const float*)d_in[17];
    const float* g_n2 = (const float*)d_in[18];
    const float* bb_n2 = (const float*)d_in[19];

    float *p_agg, *p_y, *p_scores;
    __half *p_s_h, *p_t_h, *p_wm_h, *p_x_h, *p_h1_h, *p_src_h, *p_srcc_h, *p_src0_h;
    __half *p_wsp, *p_wtp, *p_wag, *p_wl1, *p_wl2, *p_wmg;
    cudaGetSymbolAddress((void**)&p_s_h,    g_s_h);
    cudaGetSymbolAddress((void**)&p_t_h,    g_t_h);
    cudaGetSymbolAddress((void**)&p_scores, g_scores);
    cudaGetSymbolAddress((void**)&p_agg,    g_agg);
    cudaGetSymbolAddress((void**)&p_y,      g_y);
    cudaGetSymbolAddress((void**)&p_wm_h,   g_wm_h);
    cudaGetSymbolAddress((void**)&p_x_h,    g_x_h);
    cudaGetSymbolAddress((void**)&p_h1_h,   g_h1_h);
    cudaGetSymbolAddress((void**)&p_src_h,  g_src_h);
    cudaGetSymbolAddress((void**)&p_srcc_h, g_srcc_h);
    cudaGetSymbolAddress((void**)&p_src0_h, g_src0_h);
    cudaGetSymbolAddress((void**)&p_wsp,    g_wsp_h);
    cudaGetSymbolAddress((void**)&p_wtp,    g_wtp_h);
    cudaGetSymbolAddress((void**)&p_wag,    g_wag_h);
    cudaGetSymbolAddress((void**)&p_wl1,    g_wl1_h);
    cudaGetSymbolAddress((void**)&p_wl2,    g_wl2_h);
    cudaGetSymbolAddress((void**)&p_wmg,    g_wmg_h);

    cudaFuncSetAttribute(tc_gemm<1, 1, 0, 1, ND>,   cudaFuncAttributeMaxDynamicSharedMemorySize, DYN_SMEM);
    cudaFuncSetAttribute(tc_gemm<1, 1, 0, 2, ND>,   cudaFuncAttributeMaxDynamicSharedMemorySize, DYN_SMEM);
    cudaFuncSetAttribute(tc_gemm<0, 0, 1, 0, ND>,   cudaFuncAttributeMaxDynamicSharedMemorySize, DYN_SMEM);
    cudaFuncSetAttribute(tc_gemm<0, 0, 3, 0, ND>,   cudaFuncAttributeMaxDynamicSharedMemorySize, DYN_SMEM);
    cudaFuncSetAttribute(tc_gemm<1, 1, 0, 0, ND>,   cudaFuncAttributeMaxDynamicSharedMemorySize, DYN_SMEM);
    cudaFuncSetAttribute(tc_gemm<0, 0, 3, 0, NDFF>, cudaFuncAttributeMaxDynamicSharedMemorySize, DYN_SMEM);

    // one-time fp16 conversions
    f32_to_f16_kernel<<<2048, 256>>>((const float4*)in_srcc, (__half2*)p_srcc_h, NTOK * ND / 4);
    f32_to_f16_kernel<<<2048, 256>>>((const float4*)in_src,  (__half2*)p_src0_h, NTOK * ND / 4);
    f32_to_f16_kernel<<<2048, 256>>>((const float4*)w_sp, (__half2*)p_wsp, NL * ND * ND / 4);
    f32_to_f16_kernel<<<2048, 256>>>((const float4*)w_tp, (__half2*)p_wtp, NL * ND * ND / 4);
    f32_to_f16_kernel<<<2048, 256>>>((const float4*)w_ag, (__half2*)p_wag, NL * ND * ND / 4);
    f32_to_f16_kernel<<<2048, 256>>>((const float4*)w_l1, (__half2*)p_wl1, NL * NDFF * ND / 4);
    f32_to_f16_kernel<<<2048, 256>>>((const float4*)w_l2, (__half2*)p_wl2, NL * ND * NDFF / 4);
    f32_to_f16_kernel<<<192, 256>>>((const float4*)w_mg, (__half2*)p_wmg,
                                    NL * NH * NSUB * NSUB / 4);

    // hoisted: ALL layers' s = relu(srcc @ sw_l^T + sb_l) + s-part scores
    tc_gemm<1, 1, 0, 1, ND><<<dim3(ND / BN, NTOK / BM, NL), 128, DYN_SMEM>>>(
        p_srcc_h, p_wsp, b_sp, nullptr, p_s_h, nullptr, w_at, p_scores, ND);

    const dim3 gemm_dd(ND / BN, NTOK / BM);
    for (int l = 0; l < NL; l++) {
        const __half* srcA = (l == 0) ? p_src0_h : p_src_h;
        const float*  awl  = w_at + (size_t)l * NH * 2 * NSUB;
        float* sbl = p_scores + (size_t)l * NH * TT * NB;

        // t = relu(src @ tw^T + tb) [fp16 out] + ATOMIC-ADD t-part scores
        tc_gemm<1, 1, 0, 2, ND><<<gemm_dd, 128, DYN_SMEM>>>(
            srcA, p_wtp + (size_t)l * ND * ND, b_tp + l * ND,
            nullptr, p_t_h, nullptr, awl, sbl, ND);
        // weighted message via tensor cores, softmax fused in-block
        msg_mma_kernel<<<dim3(NTOK / 128, NH), 128>>>(
            p_wmg + (size_t)l * NH * NSUB * NSUB, b_mg + l * NH * NSUB,
            p_s_h + (size_t)l * NTOK * ND, sbl);
        // agg = wm @ gw^T + gb + src  [fp32 out, same-layout residual fused]
        if (l == 0)
            tc_gemm<0, 0, 1, 0, ND><<<gemm_dd, 128, DYN_SMEM>>>(
                p_wm_h, p_wag + (size_t)l * ND * ND, b_ag + l * ND,
                p_agg, nullptr, in_src, nullptr, nullptr, ND);
        else
            tc_gemm<0, 0, 3, 0, ND><<<gemm_dd, 128, DYN_SMEM>>>(
                p_wm_h, p_wag + (size_t)l * ND * ND, b_ag + l * ND,
                p_agg, nullptr, p_src_h, nullptr, nullptr, ND);
        // x = LN(agg')  [fp16 only]
        ln1_kernel<<<NTOK / 8, 256>>>(g_n1 + l * ND, bb_n1 + l * ND);
        // h1 = relu(x @ w1^T + b1)  [fp16 out]
        tc_gemm<1, 1, 0, 0, ND><<<dim3(NDFF / BN, NTOK / BM), 128, DYN_SMEM>>>(
            p_x_h, p_wl1 + (size_t)l * NDFF * ND, b_l1 + l * NDFF,
            nullptr, p_h1_h, nullptr, nullptr, nullptr, NDFF);
        // y = h1 @ w2^T + b2 + x(fp16)  [fp32 out, fp16 residual fused]
        tc_gemm<0, 0, 3, 0, NDFF><<<gemm_dd, 128, DYN_SMEM>>>(
            p_h1_h, p_wl2 + (size_t)l * ND * NDFF, b_l2 + l * ND,
            p_y, nullptr, p_x_h, nullptr, nullptr, ND);
        // out = LN(y') row p: last layer fp32 d_out, else fp16 g_src_h
        ln2_kernel<<<NTOK / 8, 256>>>(g_n2 + l * ND, bb_n2 + l * ND,
                                      (float*)d_out, (l == NL - 1) ? 0 : 1);
    }
}

// round 13
// speedup vs baseline: 1.0857x; 1.0857x over previous
#include <cuda_runtime.h>
#include <cuda_fp16.h>
#include <cstdint>
#include <cstddef>

// Problem dims
#define NL   6
#define TT   128
#define NB   256
#define ND   512
#define NH   8
#define NDFF 2048
#define NSUB 64
#define NTOK (TT * NB)   // 32768 tokens
// All activation buffers use row index p = t*NB + b ("natural" [T,B,D] order).

// mma.sync GEMM tile config (fp16 in, fp32 accum)
#define BM 128
#define BN 128
#define BKH 64                         // 64 halves = 128B row
#define NSTAGE 3
#define A_BYTES (BM * BKH * 2)         // 16384
#define STAGE_BYTES (2 * A_BYTES)      // 32768
#define DYN_SMEM (NSTAGE * STAGE_BYTES)  // 98304

// ---------------------------------------------------------------------------
// Scratch (__device__ globals; no allocation allowed)
// ---------------------------------------------------------------------------
__device__ __align__(16) __half g_s_h [(size_t)NL * NTOK * ND];  // all layers
__device__ __align__(16) __half g_t_h [(size_t)NTOK * ND];
__device__ __align__(16) float  g_scores[(size_t)NL * NH * TT * NB];
__device__ __align__(16) __half g_wm_h[(size_t)NTOK * ND];
__device__ __align__(16) float  g_agg [(size_t)NTOK * ND];   // holds src + agg
__device__ __align__(16) __half g_x_h [(size_t)NTOK * ND];
__device__ __align__(16) __half g_h1_h[(size_t)NTOK * NDFF];
__device__ __align__(16) float  g_y   [(size_t)NTOK * ND];   // holds x + y
__device__ __align__(16) __half g_src_h[(size_t)NTOK * ND];
__device__ __align__(16) __half g_srcc_h[(size_t)NTOK * ND];
__device__ __align__(16) __half g_src0_h[(size_t)NTOK * ND];
// fp16 weights
__device__ __align__(16) __half g_wsp_h[(size_t)NL * ND * ND];
__device__ __align__(16) __half g_wtp_h[(size_t)NL * ND * ND];
__device__ __align__(16) __half g_wag_h[(size_t)NL * ND * ND];
__device__ __align__(16) __half g_wl1_h[(size_t)NL * NDFF * ND];
__device__ __align__(16) __half g_wl2_h[(size_t)NL * ND * NDFF];
__device__ __align__(16) __half g_wmg_h[(size_t)NL * NH * NSUB * NSUB];

// ---------------------------------------------------------------------------
// PTX helpers (baseline sm_80+ instructions only)
// ---------------------------------------------------------------------------
__device__ __forceinline__ uint32_t smem_u32(const void* p) {
    uint32_t a;
    asm("{ .reg .u64 t; cvta.to.shared.u64 t, %1; cvt.u32.u64 %0, t; }"
        : "=r"(a) : "l"(p));
    return a;
}
__device__ __forceinline__ void cp_async16(uint32_t dst, const void* src) {
    asm volatile("cp.async.cg.shared.global [%0], [%1], 16;" :: "r"(dst), "l"(src));
}
#define CP_COMMIT() asm volatile("cp.async.commit_group;" ::: "memory")
#define CP_WAIT1()  asm volatile("cp.async.wait_group 1;" ::: "memory")
#define CP_WAIT0()  asm volatile("cp.async.wait_group 0;" ::: "memory")

__device__ __forceinline__ void ldsm_x4(uint32_t* r, uint32_t addr) {
    asm volatile("ldmatrix.sync.aligned.m8n8.x4.shared.b16 {%0,%1,%2,%3}, [%4];"
                 : "=r"(r[0]), "=r"(r[1]), "=r"(r[2]), "=r"(r[3]) : "r"(addr));
}
__device__ __forceinline__ void mma16816(float* d, const uint32_t* a,
                                         uint32_t b0, uint32_t b1) {
    asm volatile(
        "mma.sync.aligned.m16n8k16.row.col.f32.f16.f16.f32 "
        "{%0,%1,%2,%3}, {%4,%5,%6,%7}, {%8,%9}, {%0,%1,%2,%3};"
        : "+f"(d[0]), "+f"(d[1]), "+f"(d[2]), "+f"(d[3])
        : "r"(a[0]), "r"(a[1]), "r"(a[2]), "r"(a[3]), "r"(b0), "r"(b1));
}

// ---------------------------------------------------------------------------
// cooperative stage loader (128 threads): A + B tile [128 x 64h], swizzled
// ---------------------------------------------------------------------------
__device__ __forceinline__ void load_stage(const __half* __restrict__ Ag,
                                           const __half* __restrict__ Wg,
                                           int K, uint32_t abase, uint32_t bbase,
                                           int tid) {
    #pragma unroll
    for (int it = 0; it < 8; it++) {
        int q = tid + it * 128;        // 0..1023 16B chunks per operand
        int r = q >> 3;                // row 0..127
        int c = q & 7;                 // logical 16B chunk in row
        uint32_t off = (uint32_t)(r * 128 + ((c ^ (r & 7)) << 4));
        cp_async16(abase + off, Ag + (size_t)r * K + c * 8);
        cp_async16(bbase + off, Wg + (size_t)r * K + c * 8);
    }
    CP_COMMIT();
}

// fragment loader: one k16 slice for this warp (64x64 warp tile)
__device__ __forceinline__ void load_frags(uint32_t aB, uint32_t bB, int ks,
                                           int arow, int brow, int axor, int bxor,
                                           int csel,
                                           uint32_t af[4][4], uint32_t bf[4][4]) {
    #pragma unroll
    for (int mt = 0; mt < 4; mt++) {
        uint32_t addr = aB + (uint32_t)((arow + mt * 16) * 128)
                      + (uint32_t)((((ks << 1) + csel) ^ axor) << 4);
        ldsm_x4(af[mt], addr);
    }
    #pragma unroll
    for (int np = 0; np < 4; np++) {
        uint32_t addr = bB + (uint32_t)((brow + np * 16) * 128)
                      + (uint32_t)((((ks << 1) + csel) ^ bxor) << 4);
        ldsm_x4(bf[np], addr);
    }
}

// ---------------------------------------------------------------------------
// fp16 tensor-core GEMM: C[M,N] = A[M,K]@W[N,K]^T + bias (+residual), opt relu.
// ADDMODE: 0 none; 1 fp32 residual same layout; 3 fp16 residual same layout.
// SCORE:   0 none; 1 store s-part scores (BATCHED over layers via blockIdx.z);
//          2 atomicAdd t-part scores.
// grid (N/128, M/128[, NL when SCORE==1]), 128 threads (4 warps, 2x2).
// ---------------------------------------------------------------------------
template <int RELU, int OUTH, int ADDMODE, int SCORE>
__global__ __launch_bounds__(128)
void tc_gemm(const __half* __restrict__ A, const __half* __restrict__ W,
             const float* __restrict__ bias, float* __restrict__ Cf,
             __half* __restrict__ Ch, const void* __restrict__ Res,
             const float* __restrict__ aw, float* __restrict__ sbuf,
             int K, int N) {
    __shared__ float s_bias[BN];
    extern __shared__ __align__(1024) char dynsmem[];
    const uint32_t dynbase = smem_u32(dynsmem);

    if (SCORE == 1) {                  // batched over layers
        const int zl = blockIdx.z;
        W    += (size_t)zl * ND * ND;
        bias += zl * ND;
        Ch   += (size_t)zl * NTOK * ND;
        aw   += zl * NH * 2 * NSUB;
        sbuf += (size_t)zl * NH * TT * NB;
    }

    const int tid = threadIdx.x;
    const int wid = tid >> 5, lid = tid & 31;
    const int wm_ = wid >> 1, wn_ = wid & 1;
    const int m0 = blockIdx.y * BM, n0 = blockIdx.x * BN;

    s_bias[tid] = bias[n0 + tid];

    const __half* Abase = A + (size_t)m0 * K;
    const __half* Wbase = W + (size_t)n0 * K;
    const int NCH = K / BKH;

    const int sub = lid >> 3, wi = lid & 7;
    const int csel = sub >> 1;
    const int arow = wm_ * 64 + (sub & 1) * 8 + wi;
    const int brow = wn_ * 64 + (sub & 1) * 8 + wi;
    const int axor = arow & 7, bxor = brow & 7;

    #pragma unroll
    for (int c = 0; c < NSTAGE - 1; c++)
        load_stage(Abase + c * BKH, Wbase + c * BKH, K,
                   dynbase + c * STAGE_BYTES,
                   dynbase + c * STAGE_BYTES + A_BYTES, tid);

    float acc[4][8][4] = {};
    uint32_t afr[2][4][4], bfr[2][4][4];

    int stage = 0;
    for (int i = 0; i < NCH; i++) {
        CP_WAIT1();
        __syncthreads();
        int j = i + NSTAGE - 1;
        int sj = stage + NSTAGE - 1; if (sj >= NSTAGE) sj -= NSTAGE;
        if (j < NCH) {
            load_stage(Abase + j * BKH, Wbase + j * BKH, K,
                       dynbase + sj * STAGE_BYTES,
                       dynbase + sj * STAGE_BYTES + A_BYTES, tid);
        } else {
            CP_COMMIT();
        }

        const uint32_t aB = dynbase + stage * STAGE_BYTES;
        const uint32_t bB = aB + A_BYTES;

        load_frags(aB, bB, 0, arow, brow, axor, bxor, csel, afr[0], bfr[0]);
        #pragma unroll
        for (int ks = 0; ks < 4; ks++) {
            int cur = ks & 1;
            if (ks < 3)
                load_frags(aB, bB, ks + 1, arow, brow, axor, bxor, csel,
                           afr[cur ^ 1], bfr[cur ^ 1]);
            #pragma unroll
            for (int mt = 0; mt < 4; mt++)
                #pragma unroll
                for (int nt = 0; nt < 8; nt++)
                    mma16816(acc[mt][nt], afr[cur][mt],
                             bfr[cur][nt >> 1][nt & 1],
                             bfr[cur][nt >> 1][(nt & 1) + 2]);
        }
        if (++stage == NSTAGE) stage = 0;
    }

    float waw[16];
    const int shead = (n0 >> 6) + wn_;
    if (SCORE) {
        const int off = (SCORE == 2) ? 64 : 0;
        #pragma unroll
        for (int nt = 0; nt < 8; nt++) {
            int u = nt * 8 + (lid & 3) * 2;
            waw[nt * 2]     = __ldg(aw + shead * 128 + off + u);
            waw[nt * 2 + 1] = __ldg(aw + shead * 128 + off + u + 1);
        }
    }

    #pragma unroll
    for (int mt = 0; mt < 4; mt++) {
        int row = m0 + wm_ * 64 + mt * 16 + (lid >> 2);
        size_t rb0 = (size_t)row * N;
        size_t rb1 = (size_t)(row + 8) * N;
        float sc0 = 0.f, sc1 = 0.f;
        #pragma unroll
        for (int nt = 0; nt < 8; nt++) {
            int coll = wn_ * 64 + nt * 8 + (lid & 3) * 2;
            int col = n0 + coll;
            float bx = s_bias[coll], by = s_bias[coll + 1];
            float v0 = acc[mt][nt][0] + bx, v1 = acc[mt][nt][1] + by;
            float v2 = acc[mt][nt][2] + bx, v3 = acc[mt][nt][3] + by;
            if (ADDMODE == 1) {
                const float* Rf = (const float*)Res;
                float2 r0 = *(const float2*)(Rf + rb0 + col);
                float2 r1 = *(const float2*)(Rf + rb1 + col);
                v0 += r0.x; v1 += r0.y; v2 += r1.x; v3 += r1.y;
            } else if (ADDMODE == 3) {
                const __half* Rh = (const __half*)Res;
                float2 r0 = __half22float2(*(const __half2*)(Rh + rb0 + col));
                float2 r1 = __half22float2(*(const __half2*)(Rh + rb1 + col));
                v0 += r0.x; v1 += r0.y; v2 += r1.x; v3 += r1.y;
            }
            if (RELU) {
                v0 = fmaxf(v0, 0.f); v1 = fmaxf(v1, 0.f);
                v2 = fmaxf(v2, 0.f); v3 = fmaxf(v3, 0.f);
            }
            if (SCORE) {
                sc0 += v0 * waw[nt * 2] + v1 * waw[nt * 2 + 1];
                sc1 += v2 * waw[nt * 2] + v3 * waw[nt * 2 + 1];
            }
            if (OUTH) {
                *(__half2*)(Ch + (size_t)row * N + col)       = __floats2half2_rn(v0, v1);
                *(__half2*)(Ch + (size_t)(row + 8) * N + col) = __floats2half2_rn(v2, v3);
            } else {
                *(float2*)(Cf + (size_t)row * N + col)       = make_float2(v0, v1);
                *(float2*)(Cf + (size_t)(row + 8) * N + col) = make_float2(v2, v3);
            }
        }
        if (SCORE) {
            sc0 += __shfl_xor_sync(0xffffffffu, sc0, 1);
            sc0 += __shfl_xor_sync(0xffffffffu, sc0, 2);
            sc1 += __shfl_xor_sync(0xffffffffu, sc1, 1);
            sc1 += __shfl_xor_sync(0xffffffffu, sc1, 2);
            if ((lid & 3) == 0) {
                int tok0 = row, tok1 = row + 8;        // tok = t*NB + b
                int t0_ = tok0 >> 8, b0_ = tok0 & 255;
                int t1_ = tok1 >> 8, b1_ = tok1 & 255;
                float* sp0 = sbuf + (shead * TT + t0_) * NB + b0_;
                float* sp1 = sbuf + (shead * TT + t1_) * NB + b1_;
                if (SCORE == 1) { *sp0 = sc0; *sp1 = sc1; }
                else           { atomicAdd(sp0, sc0); atomicAdd(sp1, sc1); }
            }
        }
    }
}

// ---------------------------------------------------------------------------
// msg tensor-core kernel with FUSED softmax: per (head, 128 tokens) block.
// ---------------------------------------------------------------------------
__global__ __launch_bounds__(128)
void msg_mma_kernel(const __half* __restrict__ mwh,
                    const float* __restrict__ mb,
                    const __half* __restrict__ s_h,
                    const float* __restrict__ sbuf) {
    __shared__ __align__(16) __half prodS[128 * 64];
    __shared__ __align__(16) __half mwS[64 * 64];
    __shared__ float wtsS[128];
    __shared__ float mbS[64];
    __shared__ float redm[4], reds[4];

    const int h  = blockIdx.y;
    const int p0 = blockIdx.x * 128;
    const int tid = threadIdx.x;
    const int wid = tid >> 5, lid = tid & 31;

    if (tid < 64) mbS[tid] = mb[h * 64 + tid];

    {   // mw tile via cp.async (64 rows x 128B, swizzled)
        uint32_t base = smem_u32(mwS);
        #pragma unroll
        for (int it = 0; it < 4; it++) {
            int q = tid + it * 128;
            int r = q >> 3, c = q & 7;
            uint32_t off = (uint32_t)(r * 128 + ((c ^ (r & 7)) << 4));
            cp_async16(base + off, mwh + (size_t)(h * 64 + r) * 64 + c * 8);
        }
        CP_COMMIT();
    }

    {   // fused softmax over the 256-score row (h, t); t = p0/256
        const int t = p0 >> 8;
        const int boff = p0 & 255;               // 0 or 128
        const float* srow = sbuf + ((size_t)h * TT + t) * NB;
        float v0 = srow[tid];
        float v1 = srow[tid + 128];
        float mx = fmaxf(v0, v1);
        #pragma unroll
        for (int o = 16; o; o >>= 1) mx = fmaxf(mx, __shfl_xor_sync(0xffffffffu, mx, o));
        if (lid == 0) redm[wid] = mx;
        __syncthreads();
        mx = fmaxf(fmaxf(redm[0], redm[1]), fmaxf(redm[2], redm[3]));
        float e0 = __expf(v0 - mx), e1 = __expf(v1 - mx);
        float ss = e0 + e1;
        #pragma unroll
        for (int o = 16; o; o >>= 1) ss += __shfl_xor_sync(0xffffffffu, ss, o);
        if (lid == 0) reds[wid] = ss;
        __syncthreads();
        ss = (reds[0] + reds[1]) + (reds[2] + reds[3]);
        wtsS[tid] = ((boff == 0) ? e0 : e1) / ss;
    }

    {   // prod tile: s*t on load (coalesced 16B), swizzled store
        #pragma unroll
        for (int it = 0; it < 8; it++) {
            int q = tid + it * 128;
            int r = q >> 3, c = q & 7;
            size_t gidx = (size_t)(p0 + r) * ND + h * NSUB + c * 8;
            uint4 sr = *(const uint4*)(s_h + gidx);
            uint4 tr = *(const uint4*)(g_t_h + gidx);
            __half2 a0 = __hmul2(*(__half2*)&sr.x, *(__half2*)&tr.x);
            __half2 a1 = __hmul2(*(__half2*)&sr.y, *(__half2*)&tr.y);
            __half2 a2 = __hmul2(*(__half2*)&sr.z, *(__half2*)&tr.z);
            __half2 a3 = __hmul2(*(__half2*)&sr.w, *(__half2*)&tr.w);
            uint4 p4;
            p4.x = *(uint32_t*)&a0; p4.y = *(uint32_t*)&a1;
            p4.z = *(uint32_t*)&a2; p4.w = *(uint32_t*)&a3;
            uint32_t off = (uint32_t)(r * 128 + ((c ^ (r & 7)) << 4));
            *(uint4*)((char*)prodS + off) = p4;
        }
    }
    CP_WAIT0();
    __syncthreads();

    const int sub = lid >> 3, wi = lid & 7;
    const int csel = sub >> 1;
    const int arow = wid * 32 + (sub & 1) * 8 + wi;
    const int brow = (sub & 1) * 8 + wi;
    const int axor = arow & 7, bxor = brow & 7;
    const uint32_t aB = smem_u32(prodS), bB = smem_u32(mwS);

    float acc[2][8][4] = {};
    #pragma unroll
    for (int ks = 0; ks < 4; ks++) {
        uint32_t af[2][4], bf[4][4];
        #pragma unroll
        for (int mt = 0; mt < 2; mt++)
            ldsm_x4(af[mt], aB + (uint32_t)((arow + mt * 16) * 128)
                               + (uint32_t)((((ks << 1) + csel) ^ axor) << 4));
        #pragma unroll
        for (int np = 0; np < 4; np++)
            ldsm_x4(bf[np], bB + (uint32_t)((brow + np * 16) * 128)
                               + (uint32_t)((((ks << 1) + csel) ^ bxor) << 4));
        #pragma unroll
        for (int mt = 0; mt < 2; mt++)
            #pragma unroll
            for (int nt = 0; nt < 8; nt++)
                mma16816(acc[mt][nt], af[mt],
                         bf[nt >> 1][nt & 1], bf[nt >> 1][(nt & 1) + 2]);
    }

    #pragma unroll
    for (int mt = 0; mt < 2; mt++) {
        int rowl = wid * 32 + mt * 16 + (lid >> 2);
        float wt0 = wtsS[rowl], wt1 = wtsS[rowl + 8];
        size_t ob0 = (size_t)(p0 + rowl) * ND + h * NSUB;
        size_t ob1 = (size_t)(p0 + rowl + 8) * ND + h * NSUB;
        #pragma unroll
        for (int nt = 0; nt < 8; nt++) {
            int u = nt * 8 + (lid & 3) * 2;
            float m0 = acc[mt][nt][0] + mbS[u], m1 = acc[mt][nt][1] + mbS[u + 1];
            float m2 = acc[mt][nt][2] + mbS[u], m3 = acc[mt][nt][3] + mbS[u + 1];
            float v0 = fmaxf(wt0 * m0, 0.f), v1 = fmaxf(wt0 * m1, 0.f);
            float v2 = fmaxf(wt1 * m2, 0.f), v3 = fmaxf(wt1 * m3, 0.f);
            *(__half2*)(g_wm_h + ob0 + u) = __floats2half2_rn(v0, v1);
            *(__half2*)(g_wm_h + ob1 + u) = __floats2half2_rn(v2, v3);
        }
    }
}

// ---------------------------------------------------------------------------
// batched f32 -> f16 conversion: one launch for all jobs (blockIdx.y = job)
// ---------------------------------------------------------------------------
struct ConvJobs {
    const float4* in[8];
    __half2*      out[8];
    int           n4[8];
};

__global__ __launch_bounds__(256)
void f32_to_f16_multi(ConvJobs jobs) {
    const int j = blockIdx.y;
    const float4* __restrict__ in = jobs.in[j];
    __half2* __restrict__ out = jobs.out[j];
    const int n4 = jobs.n4[j];
    for (int i = blockIdx.x * 256 + threadIdx.x; i < n4; i += gridDim.x * 256) {
        float4 v = in[i];
        out[2 * i]     = __floats2half2_rn(v.x, v.y);
        out[2 * i + 1] = __floats2half2_rn(v.z, v.w);
    }
}

// ---------------------------------------------------------------------------
// Warp-per-token LayerNorms. 8 warps/block. Rows p (layout-agnostic).
// ---------------------------------------------------------------------------
__global__ __launch_bounds__(256)
void ln1_kernel(const float* __restrict__ gam, const float* __restrict__ bet) {
    const int tok = blockIdx.x * 8 + (threadIdx.x >> 5);
    const int l = threadIdx.x & 31;
    const float4* a = (const float4*)(g_agg + (size_t)tok * ND);
    float4 v[4];
    float s = 0.f;
    #pragma unroll
    for (int k = 0; k < 4; k++) {
        v[k] = a[l + 32 * k];
        s += (v[k].x + v[k].y) + (v[k].z + v[k].w);
    }
    #pragma unroll
    for (int o = 16; o; o >>= 1) s += __shfl_xor_sync(0xffffffffu, s, o);
    const float mean = s * (1.0f / ND);
    float q = 0.f;
    #pragma unroll
    for (int k = 0; k < 4; k++) {
        v[k].x -= mean; v[k].y -= mean; v[k].z -= mean; v[k].w -= mean;
        q += (v[k].x * v[k].x + v[k].y * v[k].y) + (v[k].z * v[k].z + v[k].w * v[k].w);
    }
    #pragma unroll
    for (int o = 16; o; o >>= 1) q += __shfl_xor_sync(0xffffffffu, q, o);
    const float rstd = rsqrtf(q * (1.0f / ND) + 1e-5f);
    uint2* xr = (uint2*)(g_x_h + (size_t)tok * ND);
    #pragma unroll
    for (int k = 0; k < 4; k++) {
        int idx = l + 32 * k;
        float4 gg = *(const float4*)(gam + idx * 4);
        float4 bb = *(const float4*)(bet + idx * 4);
        __half2 h0 = __floats2half2_rn(v[k].x * rstd * gg.x + bb.x,
                                       v[k].y * rstd * gg.y + bb.y);
        __half2 h1 = __floats2half2_rn(v[k].z * rstd * gg.z + bb.z,
                                       v[k].w * rstd * gg.w + bb.w);
        uint2 u; u.x = *(uint32_t*)&h0; u.y = *(uint32_t*)&h1;
        xr[idx] = u;
    }
}

__global__ __launch_bounds__(256)
void ln2_kernel(const float* __restrict__ gam, const float* __restrict__ bet,
                float* __restrict__ out, int mode) {
    const int p = blockIdx.x * 8 + (threadIdx.x >> 5);
    const int l = threadIdx.x & 31;
    const float4* a = (const float4*)(g_y + (size_t)p * ND);
    float4 v[4];
    float s = 0.f;
    #pragma unroll
    for (int k = 0; k < 4; k++) {
        v[k] = a[l + 32 * k];
        s += (v[k].x + v[k].y) + (v[k].z + v[k].w);
    }
    #pragma unroll
    for (int o = 16; o; o >>= 1) s += __shfl_xor_sync(0xffffffffu, s, o);
    const float mean = s * (1.0f / ND);
    float q = 0.f;
    #pragma unroll
    for (int k = 0; k < 4; k++) {
        v[k].x -= mean; v[k].y -= mean; v[k].z -= mean; v[k].w -= mean;
        q += (v[k].x * v[k].x + v[k].y * v[k].y) + (v[k].z * v[k].z + v[k].w * v[k].w);
    }
    #pragma unroll
    for (int o = 16; o; o >>= 1) q += __shfl_xor_sync(0xffffffffu, q, o);
    const float rstd = rsqrtf(q * (1.0f / ND) + 1e-5f);
    const size_t obase = (size_t)p * ND;
    float4* orow = (float4*)(out + obase);
    uint2*  hrow = (uint2*)(g_src_h + obase);
    #pragma unroll
    for (int k = 0; k < 4; k++) {
        int idx = l + 32 * k;
        float4 gg = *(const float4*)(gam + idx * 4);
        float4 bb = *(const float4*)(bet + idx * 4);
        float4 o4;
        o4.x = v[k].x * rstd * gg.x + bb.x;
        o4.y = v[k].y * rstd * gg.y + bb.y;
        o4.z = v[k].z * rstd * gg.z + bb.z;
        o4.w = v[k].w * rstd * gg.w + bb.w;
        if (mode == 0) {
            orow[idx] = o4;
        } else {
            __half2 h0 = __floats2half2_rn(o4.x, o4.y);
            __half2 h1 = __floats2half2_rn(o4.z, o4.w);
            uint2 u; u.x = *(uint32_t*)&h0; u.y = *(uint32_t*)&h1;
            hrow[idx] = u;
        }
    }
}

// ---------------------------------------------------------------------------
extern "C" void kernel_launch(void* const* d_in, const int* in_sizes, int n_in,
                              void* d_out, int out_size) {
    const float* in_src  = (const float*)d_in[0];
    const float* in_srcc = (const float*)d_in[1];
    const float* w_sp = (const float*)d_in[2];
    const float* b_sp = (const float*)d_in[3];
    const float* w_tp = (const float*)d_in[4];
    const float* b_tp = (const float*)d_in[5];
    const float* w_at = (const float*)d_in[6];
    const float* w_mg = (const float*)d_in[8];
    const float* b_mg = (const float*)d_in[9];
    const float* w_ag = (const float*)d_in[10];
    const float* b_ag = (const float*)d_in[11];
    const float* w_l1 = (const float*)d_in[12];
    const float* b_l1 = (const float*)d_in[13];
    const float* w_l2 = (const float*)d_in[14];
    const float* b_l2 = (const float*)d_in[15];
    const float* g_n1 = (const float*)d_in[16];
    const float* bb_n1 = (const float*)d_in[17];
    const float* g_n2 = (const float*)d_in[18];
    const float* bb_n2 = (const float*)d_in[19];

    float *p_agg, *p_y, *p_scores;
    __half *p_s_h, *p_t_h, *p_wm_h, *p_x_h, *p_h1_h, *p_src_h, *p_srcc_h, *p_src0_h;
    __half *p_wsp, *p_wtp, *p_wag, *p_wl1, *p_wl2, *p_wmg;
    cudaGetSymbolAddress((void**)&p_s_h,    g_s_h);
    cudaGetSymbolAddress((void**)&p_t_h,    g_t_h);
    cudaGetSymbolAddress((void**)&p_scores, g_scores);
    cudaGetSymbolAddress((void**)&p_agg,    g_agg);
    cudaGetSymbolAddress((void**)&p_y,      g_y);
    cudaGetSymbolAddress((void**)&p_wm_h,   g_wm_h);
    cudaGetSymbolAddress((void**)&p_x_h,    g_x_h);
    cudaGetSymbolAddress((void**)&p_h1_h,   g_h1_h);
    cudaGetSymbolAddress((void**)&p_src_h,  g_src_h);
    cudaGetSymbolAddress((void**)&p_srcc_h, g_srcc_h);
    cudaGetSymbolAddress((void**)&p_src0_h, g_src0_h);
    cudaGetSymbolAddress((void**)&p_wsp,    g_wsp_h);
    cudaGetSymbolAddress((void**)&p_wtp,    g_wtp_h);
    cudaGetSymbolAddress((void**)&p_wag,    g_wag_h);
    cudaGetSymbolAddress((void**)&p_wl1,    g_wl1_h);
    cudaGetSymbolAddress((void**)&p_wl2,    g_wl2_h);
    cudaGetSymbolAddress((void**)&p_wmg,    g_wmg_h);

    cudaFuncSetAttribute(tc_gemm<1, 1, 0, 1>, cudaFuncAttributeMaxDynamicSharedMemorySize, DYN_SMEM);
    cudaFuncSetAttribute(tc_gemm<1, 1, 0, 2>, cudaFuncAttributeMaxDynamicSharedMemorySize, DYN_SMEM);
    cudaFuncSetAttribute(tc_gemm<0, 0, 1, 0>, cudaFuncAttributeMaxDynamicSharedMemorySize, DYN_SMEM);
    cudaFuncSetAttribute(tc_gemm<1, 1, 0, 0>, cudaFuncAttributeMaxDynamicSharedMemorySize, DYN_SMEM);
    cudaFuncSetAttribute(tc_gemm<0, 0, 3, 0>, cudaFuncAttributeMaxDynamicSharedMemorySize, DYN_SMEM);

    // one-time fp16 conversions: single batched launch (8 jobs)
    {
        ConvJobs jobs;
        jobs.in[0] = (const float4*)in_srcc; jobs.out[0] = (__half2*)p_srcc_h; jobs.n4[0] = NTOK * ND / 4;
        jobs.in[1] = (const float4*)in_src;  jobs.out[1] = (__half2*)p_src0_h; jobs.n4[1] = NTOK * ND / 4;
        jobs.in[2] = (const float4*)w_sp;    jobs.out[2] = (__half2*)p_wsp;    jobs.n4[2] = NL * ND * ND / 4;
        jobs.in[3] = (const float4*)w_tp;    jobs.out[3] = (__half2*)p_wtp;    jobs.n4[3] = NL * ND * ND / 4;
        jobs.in[4] = (const float4*)w_ag;    jobs.out[4] = (__half2*)p_wag;    jobs.n4[4] = NL * ND * ND / 4;
        jobs.in[5] = (const float4*)w_l1;    jobs.out[5] = (__half2*)p_wl1;    jobs.n4[5] = NL * NDFF * ND / 4;
        jobs.in[6] = (const float4*)w_l2;    jobs.out[6] = (__half2*)p_wl2;    jobs.n4[6] = NL * ND * NDFF / 4;
        jobs.in[7] = (const float4*)w_mg;    jobs.out[7] = (__half2*)p_wmg;    jobs.n4[7] = NL * NH * NSUB * NSUB / 4;
        f32_to_f16_multi<<<dim3(512, 8), 256>>>(jobs);
    }

    // hoisted: ALL layers' s = relu(srcc @ sw_l^T + sb_l) + s-part scores
    tc_gemm<1, 1, 0, 1><<<dim3(ND / BN, NTOK / BM, NL), 128, DYN_SMEM>>>(
        p_srcc_h, p_wsp, b_sp, nullptr, p_s_h, nullptr, w_at, p_scores, ND, ND);

    const dim3 gemm_dd(ND / BN, NTOK / BM);
    for (int l = 0; l < NL; l++) {
        const __half* srcA = (l == 0) ? p_src0_h : p_src_h;
        const float*  awl  = w_at + (size_t)l * NH * 2 * NSUB;
        float* sbl = p_scores + (size_t)l * NH * TT * NB;

        // t = relu(src @ tw^T + tb) [fp16 out] + ATOMIC-ADD t-part scores
        tc_gemm<1, 1, 0, 2><<<gemm_dd, 128, DYN_SMEM>>>(
            srcA, p_wtp + (size_t)l * ND * ND, b_tp + l * ND,
            nullptr, p_t_h, nullptr, awl, sbl, ND, ND);
        // weighted message via tensor cores, softmax fused in-block
        msg_mma_kernel<<<dim3(NTOK / 128, NH), 128>>>(
            p_wmg + (size_t)l * NH * NSUB * NSUB, b_mg + l * NH * NSUB,
            p_s_h + (size_t)l * NTOK * ND, sbl);
        // agg = wm @ gw^T + gb + src  [fp32 out, same-layout residual fused]
        if (l == 0)
            tc_gemm<0, 0, 1, 0><<<gemm_dd, 128, DYN_SMEM>>>(
                p_wm_h, p_wag + (size_t)l * ND * ND, b_ag + l * ND,
                p_agg, nullptr, in_src, nullptr, nullptr, ND, ND);
        else
            tc_gemm<0, 0, 3, 0><<<gemm_dd, 128, DYN_SMEM>>>(
                p_wm_h, p_wag + (size_t)l * ND * ND, b_ag + l * ND,
                p_agg, nullptr, p_src_h, nullptr, nullptr, ND, ND);
        // x = LN(agg')  [fp16 only]
        ln1_kernel<<<NTOK / 8, 256>>>(g_n1 + l * ND, bb_n1 + l * ND);
        // h1 = relu(x @ w1^T + b1)  [fp16 out]
        tc_gemm<1, 1, 0, 0><<<dim3(NDFF / BN, NTOK / BM), 128, DYN_SMEM>>>(
            p_x_h, p_wl1 + (size_t)l * NDFF * ND, b_l1 + l * NDFF,
            nullptr, p_h1_h, nullptr, nullptr, nullptr, ND, NDFF);
        // y = h1 @ w2^T + b2 + x(fp16)  [fp32 out, fp16 residual fused]
        tc_gemm<0, 0, 3, 0><<<gemm_dd, 128, DYN_SMEM>>>(
            p_h1_h, p_wl2 + (size_t)l * ND * NDFF, b_l2 + l * ND,
            p_y, nullptr, p_x_h, nullptr, nullptr, NDFF, ND);
        // out = LN(y') row p: last layer fp32 d_out, else fp16 g_src_h
        ln2_kernel<<<NTOK / 8, 256>>>(g_n2 + l * ND, bb_n2 + l * ND,
                                      (float*)d_out, (l == NL - 1) ? 0 : 1);
    }
}

// round 14
// speedup vs baseline: 1.1047x; 1.0175x over previous
#include <cuda_runtime.h>
#include <cuda_fp16.h>
#include <cstdint>
#include <cstddef>

// Problem dims
#define NL   6
#define TT   128
#define NB   256
#define ND   512
#define NH   8
#define NDFF 2048
#define NSUB 64
#define NTOK (TT * NB)   // 32768 tokens
// All activation buffers use row index p = t*NB + b ("natural" [T,B,D] order).

// mma.sync GEMM tile config (fp16 in, fp32 accum)
#define BM 128
#define BN 128
#define BKH 64                         // 64 halves = 128B row
#define NSTAGE 3
#define A_BYTES (BM * BKH * 2)         // 16384
#define STAGE_BYTES (2 * A_BYTES)      // 32768
#define DYN_SMEM (NSTAGE * STAGE_BYTES)  // 98304

// ---------------------------------------------------------------------------
// Scratch (__device__ globals; no allocation allowed)
// ---------------------------------------------------------------------------
__device__ __align__(16) __half g_s_h [(size_t)NL * NTOK * ND];  // all layers
__device__ __align__(16) __half g_t_h [(size_t)NTOK * ND];
__device__ __align__(16) float  g_scores[(size_t)NL * NH * TT * NB];
__device__ __align__(16) __half g_wm_h[(size_t)NTOK * ND];
__device__ __align__(16) float  g_agg [(size_t)NTOK * ND];   // holds src + agg
__device__ __align__(16) __half g_x_h [(size_t)NTOK * ND];
__device__ __align__(16) __half g_h1_h[(size_t)NTOK * NDFF];
__device__ __align__(16) float  g_y   [(size_t)NTOK * ND];   // holds x + y
__device__ __align__(16) __half g_src_h[(size_t)NTOK * ND];
__device__ __align__(16) __half g_srcc_h[(size_t)NTOK * ND];
__device__ __align__(16) __half g_src0_h[(size_t)NTOK * ND];
// fp16 weights
__device__ __align__(16) __half g_wsp_h[(size_t)NL * ND * ND];
__device__ __align__(16) __half g_wtp_h[(size_t)NL * ND * ND];
__device__ __align__(16) __half g_wag_h[(size_t)NL * ND * ND];
__device__ __align__(16) __half g_wl1_h[(size_t)NL * NDFF * ND];
__device__ __align__(16) __half g_wl2_h[(size_t)NL * ND * NDFF];
__device__ __align__(16) __half g_wmg_h[(size_t)NL * NH * NSUB * NSUB];

// ---------------------------------------------------------------------------
// PTX helpers (baseline sm_80+ instructions only)
// ---------------------------------------------------------------------------
__device__ __forceinline__ uint32_t smem_u32(const void* p) {
    uint32_t a;
    asm("{ .reg .u64 t; cvta.to.shared.u64 t, %1; cvt.u32.u64 %0, t; }"
        : "=r"(a) : "l"(p));
    return a;
}
__device__ __forceinline__ void cp_async16(uint32_t dst, const void* src) {
    asm volatile("cp.async.cg.shared.global [%0], [%1], 16;" :: "r"(dst), "l"(src));
}
#define CP_COMMIT() asm volatile("cp.async.commit_group;" ::: "memory")
#define CP_WAIT1()  asm volatile("cp.async.wait_group 1;" ::: "memory")
#define CP_WAIT0()  asm volatile("cp.async.wait_group 0;" ::: "memory")

__device__ __forceinline__ void ldsm_x4(uint32_t* r, uint32_t addr) {
    asm volatile("ldmatrix.sync.aligned.m8n8.x4.shared.b16 {%0,%1,%2,%3}, [%4];"
                 : "=r"(r[0]), "=r"(r[1]), "=r"(r[2]), "=r"(r[3]) : "r"(addr));
}
__device__ __forceinline__ void mma16816(float* d, const uint32_t* a,
                                         uint32_t b0, uint32_t b1) {
    asm volatile(
        "mma.sync.aligned.m16n8k16.row.col.f32.f16.f16.f32 "
        "{%0,%1,%2,%3}, {%4,%5,%6,%7}, {%8,%9}, {%0,%1,%2,%3};"
        : "+f"(d[0]), "+f"(d[1]), "+f"(d[2]), "+f"(d[3])
        : "r"(a[0]), "r"(a[1]), "r"(a[2]), "r"(a[3]), "r"(b0), "r"(b1));
}

// ---------------------------------------------------------------------------
// cooperative stage loader (128 threads): A + B tile [128 x 64h], swizzled
// ---------------------------------------------------------------------------
__device__ __forceinline__ void load_stage(const __half* __restrict__ Ag,
                                           const __half* __restrict__ Wg,
                                           int K, uint32_t abase, uint32_t bbase,
                                           int tid) {
    #pragma unroll
    for (int it = 0; it < 8; it++) {
        int q = tid + it * 128;        // 0..1023 16B chunks per operand
        int r = q >> 3;                // row 0..127
        int c = q & 7;                 // logical 16B chunk in row
        uint32_t off = (uint32_t)(r * 128 + ((c ^ (r & 7)) << 4));
        cp_async16(abase + off, Ag + (size_t)r * K + c * 8);
        cp_async16(bbase + off, Wg + (size_t)r * K + c * 8);
    }
    CP_COMMIT();
}

// fragment loader: one k16 slice for this warp (64x64 warp tile)
__device__ __forceinline__ void load_frags(uint32_t aB, uint32_t bB, int ks,
                                           int arow, int brow, int axor, int bxor,
                                           int csel,
                                           uint32_t af[4][4], uint32_t bf[4][4]) {
    #pragma unroll
    for (int mt = 0; mt < 4; mt++) {
        uint32_t addr = aB + (uint32_t)((arow + mt * 16) * 128)
                      + (uint32_t)((((ks << 1) + csel) ^ axor) << 4);
        ldsm_x4(af[mt], addr);
    }
    #pragma unroll
    for (int np = 0; np < 4; np++) {
        uint32_t addr = bB + (uint32_t)((brow + np * 16) * 128)
                      + (uint32_t)((((ks << 1) + csel) ^ bxor) << 4);
        ldsm_x4(bf[np], addr);
    }
}

// ---------------------------------------------------------------------------
// fp16 tensor-core GEMM: C[M,N] = A[M,K]@W[N,K]^T + bias (+residual), opt relu.
// ADDMODE: 0 none; 1 fp32 residual same layout; 3 fp16 residual same layout.
// SCORE:   0 none; 1 store s-part scores (BATCHED over layers via blockIdx.z);
//          2 atomicAdd t-part scores.
// grid (N/128, M/128[, NL when SCORE==1]), 128 threads (4 warps, 2x2).
// ---------------------------------------------------------------------------
template <int RELU, int OUTH, int ADDMODE, int SCORE>
__global__ __launch_bounds__(128)
void tc_gemm(const __half* __restrict__ A, const __half* __restrict__ W,
             const float* __restrict__ bias, float* __restrict__ Cf,
             __half* __restrict__ Ch, const void* __restrict__ Res,
             const float* __restrict__ aw, float* __restrict__ sbuf,
             int K, int N) {
    __shared__ float s_bias[BN];
    extern __shared__ __align__(1024) char dynsmem[];
    const uint32_t dynbase = smem_u32(dynsmem);

    if (SCORE == 1) {                  // batched over layers
        const int zl = blockIdx.z;
        W    += (size_t)zl * ND * ND;
        bias += zl * ND;
        Ch   += (size_t)zl * NTOK * ND;
        aw   += zl * NH * 2 * NSUB;
        sbuf += (size_t)zl * NH * TT * NB;
    }

    const int tid = threadIdx.x;
    const int wid = tid >> 5, lid = tid & 31;
    const int wm_ = wid >> 1, wn_ = wid & 1;
    const int m0 = blockIdx.y * BM, n0 = blockIdx.x * BN;

    s_bias[tid] = bias[n0 + tid];

    const __half* Abase = A + (size_t)m0 * K;
    const __half* Wbase = W + (size_t)n0 * K;
    const int NCH = K / BKH;

    const int sub = lid >> 3, wi = lid & 7;
    const int csel = sub >> 1;
    const int arow = wm_ * 64 + (sub & 1) * 8 + wi;
    const int brow = wn_ * 64 + (sub & 1) * 8 + wi;
    const int axor = arow & 7, bxor = brow & 7;

    #pragma unroll
    for (int c = 0; c < NSTAGE - 1; c++)
        load_stage(Abase + c * BKH, Wbase + c * BKH, K,
                   dynbase + c * STAGE_BYTES,
                   dynbase + c * STAGE_BYTES + A_BYTES, tid);

    float acc[4][8][4] = {};
    uint32_t afr[2][4][4], bfr[2][4][4];

    int stage = 0;
    for (int i = 0; i < NCH; i++) {
        CP_WAIT1();
        __syncthreads();
        int j = i + NSTAGE - 1;
        int sj = stage + NSTAGE - 1; if (sj >= NSTAGE) sj -= NSTAGE;
        if (j < NCH) {
            load_stage(Abase + j * BKH, Wbase + j * BKH, K,
                       dynbase + sj * STAGE_BYTES,
                       dynbase + sj * STAGE_BYTES + A_BYTES, tid);
        } else {
            CP_COMMIT();
        }

        const uint32_t aB = dynbase + stage * STAGE_BYTES;
        const uint32_t bB = aB + A_BYTES;

        load_frags(aB, bB, 0, arow, brow, axor, bxor, csel, afr[0], bfr[0]);
        #pragma unroll
        for (int ks = 0; ks < 4; ks++) {
            int cur = ks & 1;
            if (ks < 3)
                load_frags(aB, bB, ks + 1, arow, brow, axor, bxor, csel,
                           afr[cur ^ 1], bfr[cur ^ 1]);
            #pragma unroll
            for (int mt = 0; mt < 4; mt++)
                #pragma unroll
                for (int nt = 0; nt < 8; nt++)
                    mma16816(acc[mt][nt], afr[cur][mt],
                             bfr[cur][nt >> 1][nt & 1],
                             bfr[cur][nt >> 1][(nt & 1) + 2]);
        }
        if (++stage == NSTAGE) stage = 0;
    }

    float waw[16];
    const int shead = (n0 >> 6) + wn_;
    if (SCORE) {
        const int off = (SCORE == 2) ? 64 : 0;
        #pragma unroll
        for (int nt = 0; nt < 8; nt++) {
            int u = nt * 8 + (lid & 3) * 2;
            waw[nt * 2]     = __ldg(aw + shead * 128 + off + u);
            waw[nt * 2 + 1] = __ldg(aw + shead * 128 + off + u + 1);
        }
    }

    #pragma unroll
    for (int mt = 0; mt < 4; mt++) {
        int row = m0 + wm_ * 64 + mt * 16 + (lid >> 2);
        size_t rb0 = (size_t)row * N;
        size_t rb1 = (size_t)(row + 8) * N;
        float sc0 = 0.f, sc1 = 0.f;
        #pragma unroll
        for (int nt = 0; nt < 8; nt++) {
            int coll = wn_ * 64 + nt * 8 + (lid & 3) * 2;
            int col = n0 + coll;
            float bx = s_bias[coll], by = s_bias[coll + 1];
            float v0 = acc[mt][nt][0] + bx, v1 = acc[mt][nt][1] + by;
            float v2 = acc[mt][nt][2] + bx, v3 = acc[mt][nt][3] + by;
            if (ADDMODE == 1) {
                const float* Rf = (const float*)Res;
                float2 r0 = *(const float2*)(Rf + rb0 + col);
                float2 r1 = *(const float2*)(Rf + rb1 + col);
                v0 += r0.x; v1 += r0.y; v2 += r1.x; v3 += r1.y;
            } else if (ADDMODE == 3) {
                const __half* Rh = (const __half*)Res;
                float2 r0 = __half22float2(*(const __half2*)(Rh + rb0 + col));
                float2 r1 = __half22float2(*(const __half2*)(Rh + rb1 + col));
                v0 += r0.x; v1 += r0.y; v2 += r1.x; v3 += r1.y;
            }
            if (RELU) {
                v0 = fmaxf(v0, 0.f); v1 = fmaxf(v1, 0.f);
                v2 = fmaxf(v2, 0.f); v3 = fmaxf(v3, 0.f);
            }
            if (SCORE) {
                sc0 += v0 * waw[nt * 2] + v1 * waw[nt * 2 + 1];
                sc1 += v2 * waw[nt * 2] + v3 * waw[nt * 2 + 1];
            }
            if (OUTH) {
                *(__half2*)(Ch + (size_t)row * N + col)       = __floats2half2_rn(v0, v1);
                *(__half2*)(Ch + (size_t)(row + 8) * N + col) = __floats2half2_rn(v2, v3);
            } else {
                *(float2*)(Cf + (size_t)row * N + col)       = make_float2(v0, v1);
                *(float2*)(Cf + (size_t)(row + 8) * N + col) = make_float2(v2, v3);
            }
        }
        if (SCORE) {
            sc0 += __shfl_xor_sync(0xffffffffu, sc0, 1);
            sc0 += __shfl_xor_sync(0xffffffffu, sc0, 2);
            sc1 += __shfl_xor_sync(0xffffffffu, sc1, 1);
            sc1 += __shfl_xor_sync(0xffffffffu, sc1, 2);
            if ((lid & 3) == 0) {
                int tok0 = row, tok1 = row + 8;        // tok = t*NB + b
                int t0_ = tok0 >> 8, b0_ = tok0 & 255;
                int t1_ = tok1 >> 8, b1_ = tok1 & 255;
                float* sp0 = sbuf + (shead * TT + t0_) * NB + b0_;
                float* sp1 = sbuf + (shead * TT + t1_) * NB + b1_;
                if (SCORE == 1) { *sp0 = sc0; *sp1 = sc1; }
                else           { atomicAdd(sp0, sc0); atomicAdd(sp1, sc1); }
            }
        }
    }
}

// ---------------------------------------------------------------------------
// msg tensor-core kernel with FUSED softmax: per (head, 128 tokens) block.
// nt-split epilogue: two passes of 4 nt each to halve live accumulators
// (regs ~88 -> ~64) and raise occupancy. Bit-identical per-element math.
// ---------------------------------------------------------------------------
__global__ __launch_bounds__(128)
void msg_mma_kernel(const __half* __restrict__ mwh,
                    const float* __restrict__ mb,
                    const __half* __restrict__ s_h,
                    const float* __restrict__ sbuf) {
    __shared__ __align__(16) __half prodS[128 * 64];
    __shared__ __align__(16) __half mwS[64 * 64];
    __shared__ float wtsS[128];
    __shared__ float mbS[64];
    __shared__ float redm[4], reds[4];

    const int h  = blockIdx.y;
    const int p0 = blockIdx.x * 128;
    const int tid = threadIdx.x;
    const int wid = tid >> 5, lid = tid & 31;

    if (tid < 64) mbS[tid] = mb[h * 64 + tid];

    {   // mw tile via cp.async (64 rows x 128B, swizzled)
        uint32_t base = smem_u32(mwS);
        #pragma unroll
        for (int it = 0; it < 4; it++) {
            int q = tid + it * 128;
            int r = q >> 3, c = q & 7;
            uint32_t off = (uint32_t)(r * 128 + ((c ^ (r & 7)) << 4));
            cp_async16(base + off, mwh + (size_t)(h * 64 + r) * 64 + c * 8);
        }
        CP_COMMIT();
    }

    {   // fused softmax over the 256-score row (h, t); t = p0/256
        const int t = p0 >> 8;
        const int boff = p0 & 255;               // 0 or 128
        const float* srow = sbuf + ((size_t)h * TT + t) * NB;
        float v0 = srow[tid];
        float v1 = srow[tid + 128];
        float mx = fmaxf(v0, v1);
        #pragma unroll
        for (int o = 16; o; o >>= 1) mx = fmaxf(mx, __shfl_xor_sync(0xffffffffu, mx, o));
        if (lid == 0) redm[wid] = mx;
        __syncthreads();
        mx = fmaxf(fmaxf(redm[0], redm[1]), fmaxf(redm[2], redm[3]));
        float e0 = __expf(v0 - mx), e1 = __expf(v1 - mx);
        float ss = e0 + e1;
        #pragma unroll
        for (int o = 16; o; o >>= 1) ss += __shfl_xor_sync(0xffffffffu, ss, o);
        if (lid == 0) reds[wid] = ss;
        __syncthreads();
        ss = (reds[0] + reds[1]) + (reds[2] + reds[3]);
        wtsS[tid] = ((boff == 0) ? e0 : e1) / ss;
    }

    {   // prod tile: s*t on load (coalesced 16B), swizzled store
        #pragma unroll
        for (int it = 0; it < 8; it++) {
            int q = tid + it * 128;
            int r = q >> 3, c = q & 7;
            size_t gidx = (size_t)(p0 + r) * ND + h * NSUB + c * 8;
            uint4 sr = *(const uint4*)(s_h + gidx);
            uint4 tr = *(const uint4*)(g_t_h + gidx);
            __half2 a0 = __hmul2(*(__half2*)&sr.x, *(__half2*)&tr.x);
            __half2 a1 = __hmul2(*(__half2*)&sr.y, *(__half2*)&tr.y);
            __half2 a2 = __hmul2(*(__half2*)&sr.z, *(__half2*)&tr.z);
            __half2 a3 = __hmul2(*(__half2*)&sr.w, *(__half2*)&tr.w);
            uint4 p4;
            p4.x = *(uint32_t*)&a0; p4.y = *(uint32_t*)&a1;
            p4.z = *(uint32_t*)&a2; p4.w = *(uint32_t*)&a3;
            uint32_t off = (uint32_t)(r * 128 + ((c ^ (r & 7)) << 4));
            *(uint4*)((char*)prodS + off) = p4;
        }
    }
    CP_WAIT0();
    __syncthreads();

    const int sub = lid >> 3, wi = lid & 7;
    const int csel = sub >> 1;
    const int arow = wid * 32 + (sub & 1) * 8 + wi;
    const int brow = (sub & 1) * 8 + wi;
    const int axor = arow & 7, bxor = brow & 7;
    const uint32_t aB = smem_u32(prodS), bB = smem_u32(mwS);

    // two nt-halves: half 0 covers nt 0..3 (np 0..1), half 1 covers nt 4..7
    #pragma unroll
    for (int half = 0; half < 2; half++) {
        float acc[2][4][4] = {};
        #pragma unroll
        for (int ks = 0; ks < 4; ks++) {
            uint32_t af[2][4], bf[2][4];
            #pragma unroll
            for (int mt = 0; mt < 2; mt++)
                ldsm_x4(af[mt], aB + (uint32_t)((arow + mt * 16) * 128)
                                   + (uint32_t)((((ks << 1) + csel) ^ axor) << 4));
            #pragma unroll
            for (int np = 0; np < 2; np++)
                ldsm_x4(bf[np], bB + (uint32_t)((brow + (half * 2 + np) * 16) * 128)
                                   + (uint32_t)((((ks << 1) + csel) ^ bxor) << 4));
            #pragma unroll
            for (int mt = 0; mt < 2; mt++)
                #pragma unroll
                for (int nt = 0; nt < 4; nt++)
                    mma16816(acc[mt][nt], af[mt],
                             bf[nt >> 1][nt & 1], bf[nt >> 1][(nt & 1) + 2]);
        }

        #pragma unroll
        for (int mt = 0; mt < 2; mt++) {
            int rowl = wid * 32 + mt * 16 + (lid >> 2);
            float wt0 = wtsS[rowl], wt1 = wtsS[rowl + 8];
            size_t ob0 = (size_t)(p0 + rowl) * ND + h * NSUB;
            size_t ob1 = (size_t)(p0 + rowl + 8) * ND + h * NSUB;
            #pragma unroll
            for (int nt = 0; nt < 4; nt++) {
                int u = (half * 4 + nt) * 8 + (lid & 3) * 2;
                float m0 = acc[mt][nt][0] + mbS[u], m1 = acc[mt][nt][1] + mbS[u + 1];
                float m2 = acc[mt][nt][2] + mbS[u], m3 = acc[mt][nt][3] + mbS[u + 1];
                float v0 = fmaxf(wt0 * m0, 0.f), v1 = fmaxf(wt0 * m1, 0.f);
                float v2 = fmaxf(wt1 * m2, 0.f), v3 = fmaxf(wt1 * m3, 0.f);
                *(__half2*)(g_wm_h + ob0 + u) = __floats2half2_rn(v0, v1);
                *(__half2*)(g_wm_h + ob1 + u) = __floats2half2_rn(v2, v3);
            }
        }
    }
}

// ---------------------------------------------------------------------------
__global__ __launch_bounds__(256)
void f32_to_f16_kernel(const float4* __restrict__ in, __half2* __restrict__ out, int n4) {
    for (int i = blockIdx.x * 256 + threadIdx.x; i < n4; i += gridDim.x * 256) {
        float4 v = in[i];
        out[2 * i]     = __floats2half2_rn(v.x, v.y);
        out[2 * i + 1] = __floats2half2_rn(v.z, v.w);
    }
}

// ---------------------------------------------------------------------------
// Warp-per-token LayerNorms. 8 warps/block. Rows p (layout-agnostic).
// ---------------------------------------------------------------------------
__global__ __launch_bounds__(256)
void ln1_kernel(const float* __restrict__ gam, const float* __restrict__ bet) {
    const int tok = blockIdx.x * 8 + (threadIdx.x >> 5);
    const int l = threadIdx.x & 31;
    const float4* a = (const float4*)(g_agg + (size_t)tok * ND);
    float4 v[4];
    float s = 0.f;
    #pragma unroll
    for (int k = 0; k < 4; k++) {
        v[k] = a[l + 32 * k];
        s += (v[k].x + v[k].y) + (v[k].z + v[k].w);
    }
    #pragma unroll
    for (int o = 16; o; o >>= 1) s += __shfl_xor_sync(0xffffffffu, s, o);
    const float mean = s * (1.0f / ND);
    float q = 0.f;
    #pragma unroll
    for (int k = 0; k < 4; k++) {
        v[k].x -= mean; v[k].y -= mean; v[k].z -= mean; v[k].w -= mean;
        q += (v[k].x * v[k].x + v[k].y * v[k].y) + (v[k].z * v[k].z + v[k].w * v[k].w);
    }
    #pragma unroll
    for (int o = 16; o; o >>= 1) q += __shfl_xor_sync(0xffffffffu, q, o);
    const float rstd = rsqrtf(q * (1.0f / ND) + 1e-5f);
    uint2* xr = (uint2*)(g_x_h + (size_t)tok * ND);
    #pragma unroll
    for (int k = 0; k < 4; k++) {
        int idx = l + 32 * k;
        float4 gg = *(const float4*)(gam + idx * 4);
        float4 bb = *(const float4*)(bet + idx * 4);
        __half2 h0 = __floats2half2_rn(v[k].x * rstd * gg.x + bb.x,
                                       v[k].y * rstd * gg.y + bb.y);
        __half2 h1 = __floats2half2_rn(v[k].z * rstd * gg.z + bb.z,
                                       v[k].w * rstd * gg.w + bb.w);
        uint2 u; u.x = *(uint32_t*)&h0; u.y = *(uint32_t*)&h1;
        xr[idx] = u;
    }
}

__global__ __launch_bounds__(256)
void ln2_kernel(const float* __restrict__ gam, const float* __restrict__ bet,
                float* __restrict__ out, int mode) {
    const int p = blockIdx.x * 8 + (threadIdx.x >> 5);
    const int l = threadIdx.x & 31;
    const float4* a = (const float4*)(g_y + (size_t)p * ND);
    float4 v[4];
    float s = 0.f;
    #pragma unroll
    for (int k = 0; k < 4; k++) {
        v[k] = a[l + 32 * k];
        s += (v[k].x + v[k].y) + (v[k].z + v[k].w);
    }
    #pragma unroll
    for (int o = 16; o; o >>= 1) s += __shfl_xor_sync(0xffffffffu, s, o);
    const float mean = s * (1.0f / ND);
    float q = 0.f;
    #pragma unroll
    for (int k = 0; k < 4; k++) {
        v[k].x -= mean; v[k].y -= mean; v[k].z -= mean; v[k].w -= mean;
        q += (v[k].x * v[k].x + v[k].y * v[k].y) + (v[k].z * v[k].z + v[k].w * v[k].w);
    }
    #pragma unroll
    for (int o = 16; o; o >>= 1) q += __shfl_xor_sync(0xffffffffu, q, o);
    const float rstd = rsqrtf(q * (1.0f / ND) + 1e-5f);
    const size_t obase = (size_t)p * ND;
    float4* orow = (float4*)(out + obase);
    uint2*  hrow = (uint2*)(g_src_h + obase);
    #pragma unroll
    for (int k = 0; k < 4; k++) {
        int idx = l + 32 * k;
        float4 gg = *(const float4*)(gam + idx * 4);
        float4 bb = *(const float4*)(bet + idx * 4);
        float4 o4;
        o4.x = v[k].x * rstd * gg.x + bb.x;
        o4.y = v[k].y * rstd * gg.y + bb.y;
        o4.z = v[k].z * rstd * gg.z + bb.z;
        o4.w = v[k].w * rstd * gg.w + bb.w;
        if (mode == 0) {
            orow[idx] = o4;
        } else {
            __half2 h0 = __floats2half2_rn(o4.x, o4.y);
            __half2 h1 = __floats2half2_rn(o4.z, o4.w);
            uint2 u; u.x = *(uint32_t*)&h0; u.y = *(uint32_t*)&h1;
            hrow[idx] = u;
        }
    }
}

// ---------------------------------------------------------------------------
extern "C" void kernel_launch(void* const* d_in, const int* in_sizes, int n_in,
                              void* d_out, int out_size) {
    const float* in_src  = (const float*)d_in[0];
    const float* in_srcc = (const float*)d_in[1];
    const float* w_sp = (const float*)d_in[2];
    const float* b_sp = (const float*)d_in[3];
    const float* w_tp = (const float*)d_in[4];
    const float* b_tp = (const float*)d_in[5];
    const float* w_at = (const float*)d_in[6];
    const float* w_mg = (const float*)d_in[8];
    const float* b_mg = (const float*)d_in[9];
    const float* w_ag = (const float*)d_in[10];
    const float* b_ag = (const float*)d_in[11];
    const float* w_l1 = (const float*)d_in[12];
    const float* b_l1 = (const float*)d_in[13];
    const float* w_l2 = (const float*)d_in[14];
    const float* b_l2 = (const float*)d_in[15];
    const float* g_n1 = (const float*)d_in[16];
    const float* bb_n1 = (const float*)d_in[17];
    const float* g_n2 = (const float*)d_in[18];
    const float* bb_n2 = (const float*)d_in[19];

    float *p_agg, *p_y, *p_scores;
    __half *p_s_h, *p_t_h, *p_wm_h, *p_x_h, *p_h1_h, *p_src_h, *p_srcc_h, *p_src0_h;
    __half *p_wsp, *p_wtp, *p_wag, *p_wl1, *p_wl2, *p_wmg;
    cudaGetSymbolAddress((void**)&p_s_h,    g_s_h);
    cudaGetSymbolAddress((void**)&p_t_h,    g_t_h);
    cudaGetSymbolAddress((void**)&p_scores, g_scores);
    cudaGetSymbolAddress((void**)&p_agg,    g_agg);
    cudaGetSymbolAddress((void**)&p_y,      g_y);
    cudaGetSymbolAddress((void**)&p_wm_h,   g_wm_h);
    cudaGetSymbolAddress((void**)&p_x_h,    g_x_h);
    cudaGetSymbolAddress((void**)&p_h1_h,   g_h1_h);
    cudaGetSymbolAddress((void**)&p_src_h,  g_src_h);
    cudaGetSymbolAddress((void**)&p_srcc_h, g_srcc_h);
    cudaGetSymbolAddress((void**)&p_src0_h, g_src0_h);
    cudaGetSymbolAddress((void**)&p_wsp,    g_wsp_h);
    cudaGetSymbolAddress((void**)&p_wtp,    g_wtp_h);
    cudaGetSymbolAddress((void**)&p_wag,    g_wag_h);
    cudaGetSymbolAddress((void**)&p_wl1,    g_wl1_h);
    cudaGetSymbolAddress((void**)&p_wl2,    g_wl2_h);
    cudaGetSymbolAddress((void**)&p_wmg,    g_wmg_h);

    cudaFuncSetAttribute(tc_gemm<1, 1, 0, 1>, cudaFuncAttributeMaxDynamicSharedMemorySize, DYN_SMEM);
    cudaFuncSetAttribute(tc_gemm<1, 1, 0, 2>, cudaFuncAttributeMaxDynamicSharedMemorySize, DYN_SMEM);
    cudaFuncSetAttribute(tc_gemm<0, 0, 1, 0>, cudaFuncAttributeMaxDynamicSharedMemorySize, DYN_SMEM);
    cudaFuncSetAttribute(tc_gemm<1, 1, 0, 0>, cudaFuncAttributeMaxDynamicSharedMemorySize, DYN_SMEM);
    cudaFuncSetAttribute(tc_gemm<0, 0, 3, 0>, cudaFuncAttributeMaxDynamicSharedMemorySize, DYN_SMEM);

    // one-time fp16 conversions (8 separate launches — proven fastest)
    f32_to_f16_kernel<<<2048, 256>>>((const float4*)in_srcc, (__half2*)p_srcc_h, NTOK * ND / 4);
    f32_to_f16_kernel<<<2048, 256>>>((const float4*)in_src,  (__half2*)p_src0_h, NTOK * ND / 4);
    f32_to_f16_kernel<<<2048, 256>>>((const float4*)w_sp, (__half2*)p_wsp, NL * ND * ND / 4);
    f32_to_f16_kernel<<<2048, 256>>>((const float4*)w_tp, (__half2*)p_wtp, NL * ND * ND / 4);
    f32_to_f16_kernel<<<2048, 256>>>((const float4*)w_ag, (__half2*)p_wag, NL * ND * ND / 4);
    f32_to_f16_kernel<<<2048, 256>>>((const float4*)w_l1, (__half2*)p_wl1, NL * NDFF * ND / 4);
    f32_to_f16_kernel<<<2048, 256>>>((const float4*)w_l2, (__half2*)p_wl2, NL * ND * NDFF / 4);
    f32_to_f16_kernel<<<192, 256>>>((const float4*)w_mg, (__half2*)p_wmg,
                                    NL * NH * NSUB * NSUB / 4);

    // hoisted: ALL layers' s = relu(srcc @ sw_l^T + sb_l) + s-part scores
    tc_gemm<1, 1, 0, 1><<<dim3(ND / BN, NTOK / BM, NL), 128, DYN_SMEM>>>(
        p_srcc_h, p_wsp, b_sp, nullptr, p_s_h, nullptr, w_at, p_scores, ND, ND);

    const dim3 gemm_dd(ND / BN, NTOK / BM);
    for (int l = 0; l < NL; l++) {
        const __half* srcA = (l == 0) ? p_src0_h : p_src_h;
        const float*  awl  = w_at + (size_t)l * NH * 2 * NSUB;
        float* sbl = p_scores + (size_t)l * NH * TT * NB;

        // t = relu(src @ tw^T + tb) [fp16 out] + ATOMIC-ADD t-part scores
        tc_gemm<1, 1, 0, 2><<<gemm_dd, 128, DYN_SMEM>>>(
            srcA, p_wtp + (size_t)l * ND * ND, b_tp + l * ND,
            nullptr, p_t_h, nullptr, awl, sbl, ND, ND);
        // weighted message via tensor cores, softmax fused in-block
        msg_mma_kernel<<<dim3(NTOK / 128, NH), 128>>>(
            p_wmg + (size_t)l * NH * NSUB * NSUB, b_mg + l * NH * NSUB,
            p_s_h + (size_t)l * NTOK * ND, sbl);
        // agg = wm @ gw^T + gb + src  [fp32 out, same-layout residual fused]
        if (l == 0)
            tc_gemm<0, 0, 1, 0><<<gemm_dd, 128, DYN_SMEM>>>(
                p_wm_h, p_wag + (size_t)l * ND * ND, b_ag + l * ND,
                p_agg, nullptr, in_src, nullptr, nullptr, ND, ND);
        else
            tc_gemm<0, 0, 3, 0><<<gemm_dd, 128, DYN_SMEM>>>(
                p_wm_h, p_wag + (size_t)l * ND * ND, b_ag + l * ND,
                p_agg, nullptr, p_src_h, nullptr, nullptr, ND, ND);
        // x = LN(agg')  [fp16 only]
        ln1_kernel<<<NTOK / 8, 256>>>(g_n1 + l * ND, bb_n1 + l * ND);
        // h1 = relu(x @ w1^T + b1)  [fp16 out]
        tc_gemm<1, 1, 0, 0><<<dim3(NDFF / BN, NTOK / BM), 128, DYN_SMEM>>>(
            p_x_h, p_wl1 + (size_t)l * NDFF * ND, b_l1 + l * NDFF,
            nullptr, p_h1_h, nullptr, nullptr, nullptr, ND, NDFF);
        // y = h1 @ w2^T + b2 + x(fp16)  [fp32 out, fp16 residual fused]
        tc_gemm<0, 0, 3, 0><<<gemm_dd, 128, DYN_SMEM>>>(
            p_h1_h, p_wl2 + (size_t)l * ND * NDFF, b_l2 + l * ND,
            p_y, nullptr, p_x_h, nullptr, nullptr, NDFF, ND);
        // out = LN(y') row p: last layer fp32 d_out, else fp16 g_src_h
        ln2_kernel<<<NTOK / 8, 256>>>(g_n2 + l * ND, bb_n2 + l * ND,
                                      (float*)d_out, (l == NL - 1) ? 0 : 1);
    }
}

// round 15
// speedup vs baseline: 1.1099x; 1.0047x over previous
#include <cuda_runtime.h>
#include <cuda_fp16.h>
#include <cstdint>
#include <cstddef>

// Problem dims
#define NL   6
#define TT   128
#define NB   256
#define ND   512
#define NH   8
#define NDFF 2048
#define NSUB 64
#define NTOK (TT * NB)   // 32768 tokens
// All activation buffers use row index p = t*NB + b ("natural" [T,B,D] order).

// mma.sync GEMM tile config (fp16 in, fp32 accum)
#define BM 128
#define BN 128
#define BKH 64                         // 64 halves = 128B row
#define NSTAGE 3
#define A_BYTES (BM * BKH * 2)         // 16384
#define STAGE_BYTES (2 * A_BYTES)      // 32768
#define DYN_SMEM (NSTAGE * STAGE_BYTES)  // 98304

// ---------------------------------------------------------------------------
// Scratch (__device__ globals; no allocation allowed)
// ---------------------------------------------------------------------------
__device__ __align__(16) __half g_s_h [(size_t)NL * NTOK * ND];  // all layers
__device__ __align__(16) __half g_t_h [(size_t)NTOK * ND];
__device__ __align__(16) float  g_scores[(size_t)NL * NH * TT * NB];
__device__ __align__(16) __half g_wm_h[(size_t)NTOK * ND];
__device__ __align__(16) float  g_agg [(size_t)NTOK * ND];   // holds src + agg
__device__ __align__(16) __half g_x_h [(size_t)NTOK * ND];
__device__ __align__(16) __half g_h1_h[(size_t)NTOK * NDFF];
__device__ __align__(16) float  g_y   [(size_t)NTOK * ND];   // holds x + y
__device__ __align__(16) __half g_src_h[(size_t)NTOK * ND];
__device__ __align__(16) __half g_srcc_h[(size_t)NTOK * ND];
__device__ __align__(16) __half g_src0_h[(size_t)NTOK * ND];
// fp16 weights
__device__ __align__(16) __half g_wsp_h[(size_t)NL * ND * ND];
__device__ __align__(16) __half g_wtp_h[(size_t)NL * ND * ND];
__device__ __align__(16) __half g_wag_h[(size_t)NL * ND * ND];
__device__ __align__(16) __half g_wl1_h[(size_t)NL * NDFF * ND];
__device__ __align__(16) __half g_wl2_h[(size_t)NL * ND * NDFF];
__device__ __align__(16) __half g_wmg_h[(size_t)NL * NH * NSUB * NSUB];

// ---------------------------------------------------------------------------
// PTX helpers (baseline sm_80+ instructions only)
// ---------------------------------------------------------------------------
__device__ __forceinline__ uint32_t smem_u32(const void* p) {
    uint32_t a;
    asm("{ .reg .u64 t; cvta.to.shared.u64 t, %1; cvt.u32.u64 %0, t; }"
        : "=r"(a) : "l"(p));
    return a;
}
__device__ __forceinline__ void cp_async16(uint32_t dst, const void* src) {
    asm volatile("cp.async.cg.shared.global [%0], [%1], 16;" :: "r"(dst), "l"(src));
}
#define CP_COMMIT() asm volatile("cp.async.commit_group;" ::: "memory")
#define CP_WAIT1()  asm volatile("cp.async.wait_group 1;" ::: "memory")
#define CP_WAIT0()  asm volatile("cp.async.wait_group 0;" ::: "memory")

__device__ __forceinline__ void ldsm_x4(uint32_t* r, uint32_t addr) {
    asm volatile("ldmatrix.sync.aligned.m8n8.x4.shared.b16 {%0,%1,%2,%3}, [%4];"
                 : "=r"(r[0]), "=r"(r[1]), "=r"(r[2]), "=r"(r[3]) : "r"(addr));
}
__device__ __forceinline__ void mma16816(float* d, const uint32_t* a,
                                         uint32_t b0, uint32_t b1) {
    asm volatile(
        "mma.sync.aligned.m16n8k16.row.col.f32.f16.f16.f32 "
        "{%0,%1,%2,%3}, {%4,%5,%6,%7}, {%8,%9}, {%0,%1,%2,%3};"
        : "+f"(d[0]), "+f"(d[1]), "+f"(d[2]), "+f"(d[3])
        : "r"(a[0]), "r"(a[1]), "r"(a[2]), "r"(a[3]), "r"(b0), "r"(b1));
}

// ---------------------------------------------------------------------------
// cooperative stage loader (128 threads): A + B tile [128 x 64h], swizzled
// ---------------------------------------------------------------------------
__device__ __forceinline__ void load_stage(const __half* __restrict__ Ag,
                                           const __half* __restrict__ Wg,
                                           int K, uint32_t abase, uint32_t bbase,
                                           int tid) {
    #pragma unroll
    for (int it = 0; it < 8; it++) {
        int q = tid + it * 128;        // 0..1023 16B chunks per operand
        int r = q >> 3;                // row 0..127
        int c = q & 7;                 // logical 16B chunk in row
        uint32_t off = (uint32_t)(r * 128 + ((c ^ (r & 7)) << 4));
        cp_async16(abase + off, Ag + (size_t)r * K + c * 8);
        cp_async16(bbase + off, Wg + (size_t)r * K + c * 8);
    }
    CP_COMMIT();
}

// fragment loader: one k16 slice for this warp (64x64 warp tile)
__device__ __forceinline__ void load_frags(uint32_t aB, uint32_t bB, int ks,
                                           int arow, int brow, int axor, int bxor,
                                           int csel,
                                           uint32_t af[4][4], uint32_t bf[4][4]) {
    #pragma unroll
    for (int mt = 0; mt < 4; mt++) {
        uint32_t addr = aB + (uint32_t)((arow + mt * 16) * 128)
                      + (uint32_t)((((ks << 1) + csel) ^ axor) << 4);
        ldsm_x4(af[mt], addr);
    }
    #pragma unroll
    for (int np = 0; np < 4; np++) {
        uint32_t addr = bB + (uint32_t)((brow + np * 16) * 128)
                      + (uint32_t)((((ks << 1) + csel) ^ bxor) << 4);
        ldsm_x4(bf[np], addr);
    }
}

// ---------------------------------------------------------------------------
// fp16 tensor-core GEMM: C[M,N] = A[M,K]@W[N,K]^T + bias (+residual), opt relu.
// ADDMODE: 0 none; 1 fp32 residual same layout; 3 fp16 residual same layout.
// SCORE:   0 none; 1 store s-part scores (BATCHED over layers via blockIdx.z);
//          2 atomicAdd t-part scores.
// grid (N/128, M/128[, NL when SCORE==1]), 128 threads (4 warps, 2x2).
// ---------------------------------------------------------------------------
template <int RELU, int OUTH, int ADDMODE, int SCORE>
__global__ __launch_bounds__(128)
void tc_gemm(const __half* __restrict__ A, const __half* __restrict__ W,
             const float* __restrict__ bias, float* __restrict__ Cf,
             __half* __restrict__ Ch, const void* __restrict__ Res,
             const float* __restrict__ aw, float* __restrict__ sbuf,
             int K, int N) {
    __shared__ float s_bias[BN];
    extern __shared__ __align__(1024) char dynsmem[];
    const uint32_t dynbase = smem_u32(dynsmem);

    if (SCORE == 1) {                  // batched over layers
        const int zl = blockIdx.z;
        W    += (size_t)zl * ND * ND;
        bias += zl * ND;
        Ch   += (size_t)zl * NTOK * ND;
        aw   += zl * NH * 2 * NSUB;
        sbuf += (size_t)zl * NH * TT * NB;
    }

    const int tid = threadIdx.x;
    const int wid = tid >> 5, lid = tid & 31;
    const int wm_ = wid >> 1, wn_ = wid & 1;
    const int m0 = blockIdx.y * BM, n0 = blockIdx.x * BN;

    s_bias[tid] = bias[n0 + tid];

    const __half* Abase = A + (size_t)m0 * K;
    const __half* Wbase = W + (size_t)n0 * K;
    const int NCH = K / BKH;

    const int sub = lid >> 3, wi = lid & 7;
    const int csel = sub >> 1;
    const int arow = wm_ * 64 + (sub & 1) * 8 + wi;
    const int brow = wn_ * 64 + (sub & 1) * 8 + wi;
    const int axor = arow & 7, bxor = brow & 7;

    #pragma unroll
    for (int c = 0; c < NSTAGE - 1; c++)
        load_stage(Abase + c * BKH, Wbase + c * BKH, K,
                   dynbase + c * STAGE_BYTES,
                   dynbase + c * STAGE_BYTES + A_BYTES, tid);

    float acc[4][8][4] = {};
    uint32_t afr[2][4][4], bfr[2][4][4];

    int stage = 0;
    for (int i = 0; i < NCH; i++) {
        CP_WAIT1();
        __syncthreads();
        int j = i + NSTAGE - 1;
        int sj = stage + NSTAGE - 1; if (sj >= NSTAGE) sj -= NSTAGE;
        if (j < NCH) {
            load_stage(Abase + j * BKH, Wbase + j * BKH, K,
                       dynbase + sj * STAGE_BYTES,
                       dynbase + sj * STAGE_BYTES + A_BYTES, tid);
        } else {
            CP_COMMIT();
        }

        const uint32_t aB = dynbase + stage * STAGE_BYTES;
        const uint32_t bB = aB + A_BYTES;

        load_frags(aB, bB, 0, arow, brow, axor, bxor, csel, afr[0], bfr[0]);
        #pragma unroll
        for (int ks = 0; ks < 4; ks++) {
            int cur = ks & 1;
            if (ks < 3)
                load_frags(aB, bB, ks + 1, arow, brow, axor, bxor, csel,
                           afr[cur ^ 1], bfr[cur ^ 1]);
            #pragma unroll
            for (int mt = 0; mt < 4; mt++)
                #pragma unroll
                for (int nt = 0; nt < 8; nt++)
                    mma16816(acc[mt][nt], afr[cur][mt],
                             bfr[cur][nt >> 1][nt & 1],
                             bfr[cur][nt >> 1][(nt & 1) + 2]);
        }
        if (++stage == NSTAGE) stage = 0;
    }

    float waw[16];
    const int shead = (n0 >> 6) + wn_;
    if (SCORE) {
        const int off = (SCORE == 2) ? 64 : 0;
        #pragma unroll
        for (int nt = 0; nt < 8; nt++) {
            int u = nt * 8 + (lid & 3) * 2;
            waw[nt * 2]     = __ldg(aw + shead * 128 + off + u);
            waw[nt * 2 + 1] = __ldg(aw + shead * 128 + off + u + 1);
        }
    }

    #pragma unroll
    for (int mt = 0; mt < 4; mt++) {
        int row = m0 + wm_ * 64 + mt * 16 + (lid >> 2);
        size_t rb0 = (size_t)row * N;
        size_t rb1 = (size_t)(row + 8) * N;
        float sc0 = 0.f, sc1 = 0.f;
        #pragma unroll
        for (int nt = 0; nt < 8; nt++) {
            int coll = wn_ * 64 + nt * 8 + (lid & 3) * 2;
            int col = n0 + coll;
            float bx = s_bias[coll], by = s_bias[coll + 1];
            float v0 = acc[mt][nt][0] + bx, v1 = acc[mt][nt][1] + by;
            float v2 = acc[mt][nt][2] + bx, v3 = acc[mt][nt][3] + by;
            if (ADDMODE == 1) {
                const float* Rf = (const float*)Res;
                float2 r0 = *(const float2*)(Rf + rb0 + col);
                float2 r1 = *(const float2*)(Rf + rb1 + col);
                v0 += r0.x; v1 += r0.y; v2 += r1.x; v3 += r1.y;
            } else if (ADDMODE == 3) {
                const __half* Rh = (const __half*)Res;
                float2 r0 = __half22float2(*(const __half2*)(Rh + rb0 + col));
                float2 r1 = __half22float2(*(const __half2*)(Rh + rb1 + col));
                v0 += r0.x; v1 += r0.y; v2 += r1.x; v3 += r1.y;
            }
            if (RELU) {
                v0 = fmaxf(v0, 0.f); v1 = fmaxf(v1, 0.f);
                v2 = fmaxf(v2, 0.f); v3 = fmaxf(v3, 0.f);
            }
            if (SCORE) {
                sc0 += v0 * waw[nt * 2] + v1 * waw[nt * 2 + 1];
                sc1 += v2 * waw[nt * 2] + v3 * waw[nt * 2 + 1];
            }
            if (OUTH) {
                *(__half2*)(Ch + (size_t)row * N + col)       = __floats2half2_rn(v0, v1);
                *(__half2*)(Ch + (size_t)(row + 8) * N + col) = __floats2half2_rn(v2, v3);
            } else {
                *(float2*)(Cf + (size_t)row * N + col)       = make_float2(v0, v1);
                *(float2*)(Cf + (size_t)(row + 8) * N + col) = make_float2(v2, v3);
            }
        }
        if (SCORE) {
            sc0 += __shfl_xor_sync(0xffffffffu, sc0, 1);
            sc0 += __shfl_xor_sync(0xffffffffu, sc0, 2);
            sc1 += __shfl_xor_sync(0xffffffffu, sc1, 1);
            sc1 += __shfl_xor_sync(0xffffffffu, sc1, 2);
            if ((lid & 3) == 0) {
                int tok0 = row, tok1 = row + 8;        // tok = t*NB + b
                int t0_ = tok0 >> 8, b0_ = tok0 & 255;
                int t1_ = tok1 >> 8, b1_ = tok1 & 255;
                float* sp0 = sbuf + (shead * TT + t0_) * NB + b0_;
                float* sp1 = sbuf + (shead * TT + t1_) * NB + b1_;
                if (SCORE == 1) { *sp0 = sc0; *sp1 = sc1; }
                else           { atomicAdd(sp0, sc0); atomicAdd(sp1, sc1); }
            }
        }
    }
}

// ---------------------------------------------------------------------------
// msg tensor-core kernel with FUSED softmax: per (head, 128 tokens) block.
// ---------------------------------------------------------------------------
__global__ __launch_bounds__(128)
void msg_mma_kernel(const __half* __restrict__ mwh,
                    const float* __restrict__ mb,
                    const __half* __restrict__ s_h,
                    const float* __restrict__ sbuf) {
    __shared__ __align__(16) __half prodS[128 * 64];
    __shared__ __align__(16) __half mwS[64 * 64];
    __shared__ float wtsS[128];
    __shared__ float mbS[64];
    __shared__ float redm[4], reds[4];

    const int h  = blockIdx.y;
    const int p0 = blockIdx.x * 128;
    const int tid = threadIdx.x;
    const int wid = tid >> 5, lid = tid & 31;

    if (tid < 64) mbS[tid] = mb[h * 64 + tid];

    {   // mw tile via cp.async (64 rows x 128B, swizzled)
        uint32_t base = smem_u32(mwS);
        #pragma unroll
        for (int it = 0; it < 4; it++) {
            int q = tid + it * 128;
            int r = q >> 3, c = q & 7;
            uint32_t off = (uint32_t)(r * 128 + ((c ^ (r & 7)) << 4));
            cp_async16(base + off, mwh + (size_t)(h * 64 + r) * 64 + c * 8);
        }
        CP_COMMIT();
    }

    {   // fused softmax over the 256-score row (h, t); t = p0/256
        const int t = p0 >> 8;
        const int boff = p0 & 255;               // 0 or 128
        const float* srow = sbuf + ((size_t)h * TT + t) * NB;
        float v0 = srow[tid];
        float v1 = srow[tid + 128];
        float mx = fmaxf(v0, v1);
        #pragma unroll
        for (int o = 16; o; o >>= 1) mx = fmaxf(mx, __shfl_xor_sync(0xffffffffu, mx, o));
        if (lid == 0) redm[wid] = mx;
        __syncthreads();
        mx = fmaxf(fmaxf(redm[0], redm[1]), fmaxf(redm[2], redm[3]));
        float e0 = __expf(v0 - mx), e1 = __expf(v1 - mx);
        float ss = e0 + e1;
        #pragma unroll
        for (int o = 16; o; o >>= 1) ss += __shfl_xor_sync(0xffffffffu, ss, o);
        if (lid == 0) reds[wid] = ss;
        __syncthreads();
        ss = (reds[0] + reds[1]) + (reds[2] + reds[3]);
        wtsS[tid] = ((boff == 0) ? e0 : e1) / ss;
    }

    {   // prod tile: s*t on load (coalesced 16B), swizzled store
        #pragma unroll
        for (int it = 0; it < 8; it++) {
            int q = tid + it * 128;
            int r = q >> 3, c = q & 7;
            size_t gidx = (size_t)(p0 + r) * ND + h * NSUB + c * 8;
            uint4 sr = *(const uint4*)(s_h + gidx);
            uint4 tr = *(const uint4*)(g_t_h + gidx);
            __half2 a0 = __hmul2(*(__half2*)&sr.x, *(__half2*)&tr.x);
            __half2 a1 = __hmul2(*(__half2*)&sr.y, *(__half2*)&tr.y);
            __half2 a2 = __hmul2(*(__half2*)&sr.z, *(__half2*)&tr.z);
            __half2 a3 = __hmul2(*(__half2*)&sr.w, *(__half2*)&tr.w);
            uint4 p4;
            p4.x = *(uint32_t*)&a0; p4.y = *(uint32_t*)&a1;
            p4.z = *(uint32_t*)&a2; p4.w = *(uint32_t*)&a3;
            uint32_t off = (uint32_t)(r * 128 + ((c ^ (r & 7)) << 4));
            *(uint4*)((char*)prodS + off) = p4;
        }
    }
    CP_WAIT0();
    __syncthreads();

    const int sub = lid >> 3, wi = lid & 7;
    const int csel = sub >> 1;
    const int arow = wid * 32 + (sub & 1) * 8 + wi;
    const int brow = (sub & 1) * 8 + wi;
    const int axor = arow & 7, bxor = brow & 7;
    const uint32_t aB = smem_u32(prodS), bB = smem_u32(mwS);

    float acc[2][8][4] = {};
    #pragma unroll
    for (int ks = 0; ks < 4; ks++) {
        uint32_t af[2][4], bf[4][4];
        #pragma unroll
        for (int mt = 0; mt < 2; mt++)
            ldsm_x4(af[mt], aB + (uint32_t)((arow + mt * 16) * 128)
                               + (uint32_t)((((ks << 1) + csel) ^ axor) << 4));
        #pragma unroll
        for (int np = 0; np < 4; np++)
            ldsm_x4(bf[np], bB + (uint32_t)((brow + np * 16) * 128)
                               + (uint32_t)((((ks << 1) + csel) ^ bxor) << 4));
        #pragma unroll
        for (int mt = 0; mt < 2; mt++)
            #pragma unroll
            for (int nt = 0; nt < 8; nt++)
                mma16816(acc[mt][nt], af[mt],
                         bf[nt >> 1][nt & 1], bf[nt >> 1][(nt & 1) + 2]);
    }

    #pragma unroll
    for (int mt = 0; mt < 2; mt++) {
        int rowl = wid * 32 + mt * 16 + (lid >> 2);
        float wt0 = wtsS[rowl], wt1 = wtsS[rowl + 8];
        size_t ob0 = (size_t)(p0 + rowl) * ND + h * NSUB;
        size_t ob1 = (size_t)(p0 + rowl + 8) * ND + h * NSUB;
        #pragma unroll
        for (int nt = 0; nt < 8; nt++) {
            int u = nt * 8 + (lid & 3) * 2;
            float m0 = acc[mt][nt][0] + mbS[u], m1 = acc[mt][nt][1] + mbS[u + 1];
            float m2 = acc[mt][nt][2] + mbS[u], m3 = acc[mt][nt][3] + mbS[u + 1];
            float v0 = fmaxf(wt0 * m0, 0.f), v1 = fmaxf(wt0 * m1, 0.f);
            float v2 = fmaxf(wt1 * m2, 0.f), v3 = fmaxf(wt1 * m3, 0.f);
            *(__half2*)(g_wm_h + ob0 + u) = __floats2half2_rn(v0, v1);
            *(__half2*)(g_wm_h + ob1 + u) = __floats2half2_rn(v2, v3);
        }
    }
}

// ---------------------------------------------------------------------------
__global__ __launch_bounds__(256)
void f32_to_f16_kernel(const float4* __restrict__ in, __half2* __restrict__ out, int n4) {
    for (int i = blockIdx.x * 256 + threadIdx.x; i < n4; i += gridDim.x * 256) {
        float4 v = in[i];
        out[2 * i]     = __floats2half2_rn(v.x, v.y);
        out[2 * i + 1] = __floats2half2_rn(v.z, v.w);
    }
}

// ---------------------------------------------------------------------------
// Warp-per-token LayerNorms. 8 warps/block. Rows p (layout-agnostic).
// ---------------------------------------------------------------------------
__global__ __launch_bounds__(256)
void ln1_kernel(const float* __restrict__ gam, const float* __restrict__ bet) {
    const int tok = blockIdx.x * 8 + (threadIdx.x >> 5);
    const int l = threadIdx.x & 31;
    const float4* a = (const float4*)(g_agg + (size_t)tok * ND);
    float4 v[4];
    float s = 0.f;
    #pragma unroll
    for (int k = 0; k < 4; k++) {
        v[k] = a[l + 32 * k];
        s += (v[k].x + v[k].y) + (v[k].z + v[k].w);
    }
    #pragma unroll
    for (int o = 16; o; o >>= 1) s += __shfl_xor_sync(0xffffffffu, s, o);
    const float mean = s * (1.0f / ND);
    float q = 0.f;
    #pragma unroll
    for (int k = 0; k < 4; k++) {
        v[k].x -= mean; v[k].y -= mean; v[k].z -= mean; v[k].w -= mean;
        q += (v[k].x * v[k].x + v[k].y * v[k].y) + (v[k].z * v[k].z + v[k].w * v[k].w);
    }
    #pragma unroll
    for (int o = 16; o; o >>= 1) q += __shfl_xor_sync(0xffffffffu, q, o);
    const float rstd = rsqrtf(q * (1.0f / ND) + 1e-5f);
    uint2* xr = (uint2*)(g_x_h + (size_t)tok * ND);
    #pragma unroll
    for (int k = 0; k < 4; k++) {
        int idx = l + 32 * k;
        float4 gg = *(const float4*)(gam + idx * 4);
        float4 bb = *(const float4*)(bet + idx * 4);
        __half2 h0 = __floats2half2_rn(v[k].x * rstd * gg.x + bb.x,
                                       v[k].y * rstd * gg.y + bb.y);
        __half2 h1 = __floats2half2_rn(v[k].z * rstd * gg.z + bb.z,
                                       v[k].w * rstd * gg.w + bb.w);
        uint2 u; u.x = *(uint32_t*)&h0; u.y = *(uint32_t*)&h1;
        xr[idx] = u;
    }
}

__global__ __launch_bounds__(256)
void ln2_kernel(const float* __restrict__ gam, const float* __restrict__ bet,
                float* __restrict__ out, int mode) {
    const int p = blockIdx.x * 8 + (threadIdx.x >> 5);
    const int l = threadIdx.x & 31;
    const float4* a = (const float4*)(g_y + (size_t)p * ND);
    float4 v[4];
    float s = 0.f;
    #pragma unroll
    for (int k = 0; k < 4; k++) {
        v[k] = a[l + 32 * k];
        s += (v[k].x + v[k].y) + (v[k].z + v[k].w);
    }
    #pragma unroll
    for (int o = 16; o; o >>= 1) s += __shfl_xor_sync(0xffffffffu, s, o);
    const float mean = s * (1.0f / ND);
    float q = 0.f;
    #pragma unroll
    for (int k = 0; k < 4; k++) {
        v[k].x -= mean; v[k].y -= mean; v[k].z -= mean; v[k].w -= mean;
        q += (v[k].x * v[k].x + v[k].y * v[k].y) + (v[k].z * v[k].z + v[k].w * v[k].w);
    }
    #pragma unroll
    for (int o = 16; o; o >>= 1) q += __shfl_xor_sync(0xffffffffu, q, o);
    const float rstd = rsqrtf(q * (1.0f / ND) + 1e-5f);
    const size_t obase = (size_t)p * ND;
    float4* orow = (float4*)(out + obase);
    uint2*  hrow = (uint2*)(g_src_h + obase);
    #pragma unroll
    for (int k = 0; k < 4; k++) {
        int idx = l + 32 * k;
        float4 gg = *(const float4*)(gam + idx * 4);
        float4 bb = *(const float4*)(bet + idx * 4);
        float4 o4;
        o4.x = v[k].x * rstd * gg.x + bb.x;
        o4.y = v[k].y * rstd * gg.y + bb.y;
        o4.z = v[k].z * rstd * gg.z + bb.z;
        o4.w = v[k].w * rstd * gg.w + bb.w;
        if (mode == 0) {
            orow[idx] = o4;
        } else {
            __half2 h0 = __floats2half2_rn(o4.x, o4.y);
            __half2 h1 = __floats2half2_rn(o4.z, o4.w);
            uint2 u; u.x = *(uint32_t*)&h0; u.y = *(uint32_t*)&h1;
            hrow[idx] = u;
        }
    }
}

// ---------------------------------------------------------------------------
extern "C" void kernel_launch(void* const* d_in, const int* in_sizes, int n_in,
                              void* d_out, int out_size) {
    const float* in_src  = (const float*)d_in[0];
    const float* in_srcc = (const float*)d_in[1];
    const float* w_sp = (const float*)d_in[2];
    const float* b_sp = (const float*)d_in[3];
    const float* w_tp = (const float*)d_in[4];
    const float* b_tp = (const float*)d_in[5];
    const float* w_at = (const float*)d_in[6];
    const float* w_mg = (const float*)d_in[8];
    const float* b_mg = (const float*)d_in[9];
    const float* w_ag = (const float*)d_in[10];
    const float* b_ag = (const float*)d_in[11];
    const float* w_l1 = (const float*)d_in[12];
    const float* b_l1 = (const float*)d_in[13];
    const float* w_l2 = (const float*)d_in[14];
    const float* b_l2 = (const float*)d_in[15];
    const float* g_n1 = (const float*)d_in[16];
    const float* bb_n1 = (const float*)d_in[17];
    const float* g_n2 = (const float*)d_in[18];
    const float* bb_n2 = (const float*)d_in[19];

    float *p_agg, *p_y, *p_scores;
    __half *p_s_h, *p_t_h, *p_wm_h, *p_x_h, *p_h1_h, *p_src_h, *p_srcc_h, *p_src0_h;
    __half *p_wsp, *p_wtp, *p_wag, *p_wl1, *p_wl2, *p_wmg;
    cudaGetSymbolAddress((void**)&p_s_h,    g_s_h);
    cudaGetSymbolAddress((void**)&p_t_h,    g_t_h);
    cudaGetSymbolAddress((void**)&p_scores, g_scores);
    cudaGetSymbolAddress((void**)&p_agg,    g_agg);
    cudaGetSymbolAddress((void**)&p_y,      g_y);
    cudaGetSymbolAddress((void**)&p_wm_h,   g_wm_h);
    cudaGetSymbolAddress((void**)&p_x_h,    g_x_h);
    cudaGetSymbolAddress((void**)&p_h1_h,   g_h1_h);
    cudaGetSymbolAddress((void**)&p_src_h,  g_src_h);
    cudaGetSymbolAddress((void**)&p_srcc_h, g_srcc_h);
    cudaGetSymbolAddress((void**)&p_src0_h, g_src0_h);
    cudaGetSymbolAddress((void**)&p_wsp,    g_wsp_h);
    cudaGetSymbolAddress((void**)&p_wtp,    g_wtp_h);
    cudaGetSymbolAddress((void**)&p_wag,    g_wag_h);
    cudaGetSymbolAddress((void**)&p_wl1,    g_wl1_h);
    cudaGetSymbolAddress((void**)&p_wl2,    g_wl2_h);
    cudaGetSymbolAddress((void**)&p_wmg,    g_wmg_h);

    cudaFuncSetAttribute(tc_gemm<1, 1, 0, 1>, cudaFuncAttributeMaxDynamicSharedMemorySize, DYN_SMEM);
    cudaFuncSetAttribute(tc_gemm<1, 1, 0, 2>, cudaFuncAttributeMaxDynamicSharedMemorySize, DYN_SMEM);
    cudaFuncSetAttribute(tc_gemm<0, 0, 1, 0>, cudaFuncAttributeMaxDynamicSharedMemorySize, DYN_SMEM);
    cudaFuncSetAttribute(tc_gemm<1, 1, 0, 0>, cudaFuncAttributeMaxDynamicSharedMemorySize, DYN_SMEM);
    cudaFuncSetAttribute(tc_gemm<0, 0, 3, 0>, cudaFuncAttributeMaxDynamicSharedMemorySize, DYN_SMEM);

    // one-time fp16 conversions (8 separate launches — proven fastest)
    f32_to_f16_kernel<<<2048, 256>>>((const float4*)in_srcc, (__half2*)p_srcc_h, NTOK * ND / 4);
    f32_to_f16_kernel<<<2048, 256>>>((const float4*)in_src,  (__half2*)p_src0_h, NTOK * ND / 4);
    f32_to_f16_kernel<<<2048, 256>>>((const float4*)w_sp, (__half2*)p_wsp, NL * ND * ND / 4);
    f32_to_f16_kernel<<<2048, 256>>>((const float4*)w_tp, (__half2*)p_wtp, NL * ND * ND / 4);
    f32_to_f16_kernel<<<2048, 256>>>((const float4*)w_ag, (__half2*)p_wag, NL * ND * ND / 4);
    f32_to_f16_kernel<<<2048, 256>>>((const float4*)w_l1, (__half2*)p_wl1, NL * NDFF * ND / 4);
    f32_to_f16_kernel<<<2048, 256>>>((const float4*)w_l2, (__half2*)p_wl2, NL * ND * NDFF / 4);
    f32_to_f16_kernel<<<192, 256>>>((const float4*)w_mg, (__half2*)p_wmg,
                                    NL * NH * NSUB * NSUB / 4);

    // hoisted: ALL layers' s = relu(srcc @ sw_l^T + sb_l) + s-part scores
    tc_gemm<1, 1, 0, 1><<<dim3(ND / BN, NTOK / BM, NL), 128, DYN_SMEM>>>(
        p_srcc_h, p_wsp, b_sp, nullptr, p_s_h, nullptr, w_at, p_scores, ND, ND);

    const dim3 gemm_dd(ND / BN, NTOK / BM);
    for (int l = 0; l < NL; l++) {
        const __half* srcA = (l == 0) ? p_src0_h : p_src_h;
        const float*  awl  = w_at + (size_t)l * NH * 2 * NSUB;
        float* sbl = p_scores + (size_t)l * NH * TT * NB;

        // t = relu(src @ tw^T + tb) [fp16 out] + ATOMIC-ADD t-part scores
        tc_gemm<1, 1, 0, 2><<<gemm_dd, 128, DYN_SMEM>>>(
            srcA, p_wtp + (size_t)l * ND * ND, b_tp + l * ND,
            nullptr, p_t_h, nullptr, awl, sbl, ND, ND);
        // weighted message via tensor cores, softmax fused in-block
        msg_mma_kernel<<<dim3(NTOK / 128, NH), 128>>>(
            p_wmg + (size_t)l * NH * NSUB * NSUB, b_mg + l * NH * NSUB,
            p_s_h + (size_t)l * NTOK * ND, sbl);
        // agg = wm @ gw^T + gb + src  [fp32 out, same-layout residual fused]
        if (l == 0)
            tc_gemm<0, 0, 1, 0><<<gemm_dd, 128, DYN_SMEM>>>(
                p_wm_h, p_wag + (size_t)l * ND * ND, b_ag + l * ND,
                p_agg, nullptr, in_src, nullptr, nullptr, ND, ND);
        else
            tc_gemm<0, 0, 3, 0><<<gemm_dd, 128, DYN_SMEM>>>(
                p_wm_h, p_wag + (size_t)l * ND * ND, b_ag + l * ND,
                p_agg, nullptr, p_src_h, nullptr, nullptr, ND, ND);
        // x = LN(agg')  [fp16 only]
        ln1_kernel<<<NTOK / 8, 256>>>(g_n1 + l * ND, bb_n1 + l * ND);
        // h1 = relu(x @ w1^T + b1)  [fp16 out]
        tc_gemm<1, 1, 0, 0><<<dim3(NDFF / BN, NTOK / BM), 128, DYN_SMEM>>>(
            p_x_h, p_wl1 + (size_t)l * NDFF * ND, b_l1 + l * NDFF,
            nullptr, p_h1_h, nullptr, nullptr, nullptr, ND, NDFF);
        // y = h1 @ w2^T + b2 + x(fp16)  [fp32 out, fp16 residual fused]
        tc_gemm<0, 0, 3, 0><<<gemm_dd, 128, DYN_SMEM>>>(
            p_h1_h, p_wl2 + (size_t)l * ND * NDFF, b_l2 + l * ND,
            p_y, nullptr, p_x_h, nullptr, nullptr, NDFF, ND);
        // out = LN(y') row p: last layer fp32 d_out, else fp16 g_src_h
        ln2_kernel<<<NTOK / 8, 256>>>(g_n2 + l * ND, bb_n2 + l * ND,
                                      (float*)d_out, (l == NL - 1) ? 0 : 1);
    }
}

// round 16
// speedup vs baseline: 1.1128x; 1.0026x over previous
#include <cuda_runtime.h>
#include <cuda_fp16.h>
#include <cstdint>
#include <cstddef>

// Problem dims
#define NL   6
#define TT   128
#define NB   256
#define ND   512
#define NH   8
#define NDFF 2048
#define NSUB 64
#define NTOK (TT * NB)   // 32768 tokens
// All activation buffers use row index p = t*NB + b ("natural" [T,B,D] order).

// mma.sync GEMM tile config (fp16 in, fp32 accum)
#define BM 128
#define BN 128
#define BKH 64                         // 64 halves = 128B row
#define NSTAGE 3
#define A_BYTES (BM * BKH * 2)         // 16384
#define STAGE_BYTES (2 * A_BYTES)      // 32768
#define DYN_SMEM (NSTAGE * STAGE_BYTES)  // 98304

// ---------------------------------------------------------------------------
// Scratch (__device__ globals; no allocation allowed)
// ---------------------------------------------------------------------------
__device__ __align__(16) __half g_s_h [(size_t)NL * NTOK * ND];  // all layers
__device__ __align__(16) __half g_t_h [(size_t)NTOK * ND];
__device__ __align__(16) float  g_scores[(size_t)NL * NH * TT * NB];
__device__ __align__(16) __half g_wm_h[(size_t)NTOK * ND];
__device__ __align__(16) float  g_agg [(size_t)NTOK * ND];   // holds src + agg
__device__ __align__(16) __half g_x_h [(size_t)NTOK * ND];
__device__ __align__(16) __half g_h1_h[(size_t)NTOK * NDFF];
__device__ __align__(16) float  g_y   [(size_t)NTOK * ND];   // holds x + y
__device__ __align__(16) __half g_src_h[(size_t)NTOK * ND];
__device__ __align__(16) __half g_srcc_h[(size_t)NTOK * ND];
__device__ __align__(16) __half g_src0_h[(size_t)NTOK * ND];
// fp16 weights
__device__ __align__(16) __half g_wsp_h[(size_t)NL * ND * ND];
__device__ __align__(16) __half g_wtp_h[(size_t)NL * ND * ND];
__device__ __align__(16) __half g_wag_h[(size_t)NL * ND * ND];
__device__ __align__(16) __half g_wl1_h[(size_t)NL * NDFF * ND];
__device__ __align__(16) __half g_wl2_h[(size_t)NL * ND * NDFF];
__device__ __align__(16) __half g_wmg_h[(size_t)NL * NH * NSUB * NSUB];

// ---------------------------------------------------------------------------
// PTX helpers (baseline sm_80+ instructions only)
// ---------------------------------------------------------------------------
__device__ __forceinline__ uint32_t smem_u32(const void* p) {
    uint32_t a;
    asm("{ .reg .u64 t; cvta.to.shared.u64 t, %1; cvt.u32.u64 %0, t; }"
        : "=r"(a) : "l"(p));
    return a;
}
__device__ __forceinline__ void cp_async16(uint32_t dst, const void* src) {
    asm volatile("cp.async.cg.shared.global [%0], [%1], 16;" :: "r"(dst), "l"(src));
}
#define CP_COMMIT() asm volatile("cp.async.commit_group;" ::: "memory")
#define CP_WAIT1()  asm volatile("cp.async.wait_group 1;" ::: "memory")
#define CP_WAIT0()  asm volatile("cp.async.wait_group 0;" ::: "memory")

__device__ __forceinline__ void ldsm_x4(uint32_t* r, uint32_t addr) {
    asm volatile("ldmatrix.sync.aligned.m8n8.x4.shared.b16 {%0,%1,%2,%3}, [%4];"
                 : "=r"(r[0]), "=r"(r[1]), "=r"(r[2]), "=r"(r[3]) : "r"(addr));
}
__device__ __forceinline__ void mma16816(float* d, const uint32_t* a,
                                         uint32_t b0, uint32_t b1) {
    asm volatile(
        "mma.sync.aligned.m16n8k16.row.col.f32.f16.f16.f32 "
        "{%0,%1,%2,%3}, {%4,%5,%6,%7}, {%8,%9}, {%0,%1,%2,%3};"
        : "+f"(d[0]), "+f"(d[1]), "+f"(d[2]), "+f"(d[3])
        : "r"(a[0]), "r"(a[1]), "r"(a[2]), "r"(a[3]), "r"(b0), "r"(b1));
}

// ---------------------------------------------------------------------------
// cooperative stage loader (128 threads): A + B tile [128 x 64h], swizzled
// ---------------------------------------------------------------------------
__device__ __forceinline__ void load_stage(const __half* __restrict__ Ag,
                                           const __half* __restrict__ Wg,
                                           int K, uint32_t abase, uint32_t bbase,
                                           int tid) {
    #pragma unroll
    for (int it = 0; it < 8; it++) {
        int q = tid + it * 128;        // 0..1023 16B chunks per operand
        int r = q >> 3;                // row 0..127
        int c = q & 7;                 // logical 16B chunk in row
        uint32_t off = (uint32_t)(r * 128 + ((c ^ (r & 7)) << 4));
        cp_async16(abase + off, Ag + (size_t)r * K + c * 8);
        cp_async16(bbase + off, Wg + (size_t)r * K + c * 8);
    }
    CP_COMMIT();
}

// fragment loader: one k16 slice for this warp (64x64 warp tile)
__device__ __forceinline__ void load_frags(uint32_t aB, uint32_t bB, int ks,
                                           int arow, int brow, int axor, int bxor,
                                           int csel,
                                           uint32_t af[4][4], uint32_t bf[4][4]) {
    #pragma unroll
    for (int mt = 0; mt < 4; mt++) {
        uint32_t addr = aB + (uint32_t)((arow + mt * 16) * 128)
                      + (uint32_t)((((ks << 1) + csel) ^ axor) << 4);
        ldsm_x4(af[mt], addr);
    }
    #pragma unroll
    for (int np = 0; np < 4; np++) {
        uint32_t addr = bB + (uint32_t)((brow + np * 16) * 128)
                      + (uint32_t)((((ks << 1) + csel) ^ bxor) << 4);
        ldsm_x4(bf[np], addr);
    }
}

// ---------------------------------------------------------------------------
// fp16 tensor-core GEMM: C[M,N] = A[M,K]@W[N,K]^T + bias (+residual), opt relu.
// ADDMODE: 0 none; 1 fp32 residual same layout; 3 fp16 residual same layout.
// SCORE:   0 none; 1 store s-part scores (BATCHED over layers via blockIdx.z);
//          2 atomicAdd t-part scores.
// grid (N/128, M/128[, NL when SCORE==1]), 128 threads (4 warps, 2x2).
// ---------------------------------------------------------------------------
template <int RELU, int OUTH, int ADDMODE, int SCORE>
__global__ __launch_bounds__(128)
void tc_gemm(const __half* __restrict__ A, const __half* __restrict__ W,
             const float* __restrict__ bias, float* __restrict__ Cf,
             __half* __restrict__ Ch, const void* __restrict__ Res,
             const float* __restrict__ aw, float* __restrict__ sbuf,
             int K, int N) {
    __shared__ float s_bias[BN];
    extern __shared__ __align__(1024) char dynsmem[];
    const uint32_t dynbase = smem_u32(dynsmem);

    if (SCORE == 1) {                  // batched over layers
        const int zl = blockIdx.z;
        W    += (size_t)zl * ND * ND;
        bias += zl * ND;
        Ch   += (size_t)zl * NTOK * ND;
        aw   += zl * NH * 2 * NSUB;
        sbuf += (size_t)zl * NH * TT * NB;
    }

    const int tid = threadIdx.x;
    const int wid = tid >> 5, lid = tid & 31;
    const int wm_ = wid >> 1, wn_ = wid & 1;
    const int m0 = blockIdx.y * BM, n0 = blockIdx.x * BN;

    s_bias[tid] = bias[n0 + tid];

    const __half* Abase = A + (size_t)m0 * K;
    const __half* Wbase = W + (size_t)n0 * K;
    const int NCH = K / BKH;

    const int sub = lid >> 3, wi = lid & 7;
    const int csel = sub >> 1;
    const int arow = wm_ * 64 + (sub & 1) * 8 + wi;
    const int brow = wn_ * 64 + (sub & 1) * 8 + wi;
    const int axor = arow & 7, bxor = brow & 7;

    #pragma unroll
    for (int c = 0; c < NSTAGE - 1; c++)
        load_stage(Abase + c * BKH, Wbase + c * BKH, K,
                   dynbase + c * STAGE_BYTES,
                   dynbase + c * STAGE_BYTES + A_BYTES, tid);

    float acc[4][8][4] = {};
    uint32_t afr[2][4][4], bfr[2][4][4];

    int stage = 0;
    for (int i = 0; i < NCH; i++) {
        CP_WAIT1();
        __syncthreads();
        int j = i + NSTAGE - 1;
        int sj = stage + NSTAGE - 1; if (sj >= NSTAGE) sj -= NSTAGE;
        if (j < NCH) {
            load_stage(Abase + j * BKH, Wbase + j * BKH, K,
                       dynbase + sj * STAGE_BYTES,
                       dynbase + sj * STAGE_BYTES + A_BYTES, tid);
        } else {
            CP_COMMIT();
        }

        const uint32_t aB = dynbase + stage * STAGE_BYTES;
        const uint32_t bB = aB + A_BYTES;

        load_frags(aB, bB, 0, arow, brow, axor, bxor, csel, afr[0], bfr[0]);
        #pragma unroll
        for (int ks = 0; ks < 4; ks++) {
            int cur = ks & 1;
            if (ks < 3)
                load_frags(aB, bB, ks + 1, arow, brow, axor, bxor, csel,
                           afr[cur ^ 1], bfr[cur ^ 1]);
            #pragma unroll
            for (int mt = 0; mt < 4; mt++)
                #pragma unroll
                for (int nt = 0; nt < 8; nt++)
                    mma16816(acc[mt][nt], afr[cur][mt],
                             bfr[cur][nt >> 1][nt & 1],
                             bfr[cur][nt >> 1][(nt & 1) + 2]);
        }
        if (++stage == NSTAGE) stage = 0;
    }

    float waw[16];
    const int shead = (n0 >> 6) + wn_;
    if (SCORE) {
        const int off = (SCORE == 2) ? 64 : 0;
        #pragma unroll
        for (int nt = 0; nt < 8; nt++) {
            int u = nt * 8 + (lid & 3) * 2;
            waw[nt * 2]     = __ldg(aw + shead * 128 + off + u);
            waw[nt * 2 + 1] = __ldg(aw + shead * 128 + off + u + 1);
        }
    }

    #pragma unroll
    for (int mt = 0; mt < 4; mt++) {
        int row = m0 + wm_ * 64 + mt * 16 + (lid >> 2);
        size_t rb0 = (size_t)row * N;
        size_t rb1 = (size_t)(row + 8) * N;
        float sc0 = 0.f, sc1 = 0.f;
        #pragma unroll
        for (int nt = 0; nt < 8; nt++) {
            int coll = wn_ * 64 + nt * 8 + (lid & 3) * 2;
            int col = n0 + coll;
            float bx = s_bias[coll], by = s_bias[coll + 1];
            float v0 = acc[mt][nt][0] + bx, v1 = acc[mt][nt][1] + by;
            float v2 = acc[mt][nt][2] + bx, v3 = acc[mt][nt][3] + by;
            if (ADDMODE == 1) {
                const float* Rf = (const float*)Res;
                float2 r0 = *(const float2*)(Rf + rb0 + col);
                float2 r1 = *(const float2*)(Rf + rb1 + col);
                v0 += r0.x; v1 += r0.y; v2 += r1.x; v3 += r1.y;
            } else if (ADDMODE == 3) {
                const __half* Rh = (const __half*)Res;
                float2 r0 = __half22float2(*(const __half2*)(Rh + rb0 + col));
                float2 r1 = __half22float2(*(const __half2*)(Rh + rb1 + col));
                v0 += r0.x; v1 += r0.y; v2 += r1.x; v3 += r1.y;
            }
            if (RELU) {
                v0 = fmaxf(v0, 0.f); v1 = fmaxf(v1, 0.f);
                v2 = fmaxf(v2, 0.f); v3 = fmaxf(v3, 0.f);
            }
            if (SCORE) {
                sc0 += v0 * waw[nt * 2] + v1 * waw[nt * 2 + 1];
                sc1 += v2 * waw[nt * 2] + v3 * waw[nt * 2 + 1];
            }
            if (OUTH) {
                *(__half2*)(Ch + (size_t)row * N + col)       = __floats2half2_rn(v0, v1);
                *(__half2*)(Ch + (size_t)(row + 8) * N + col) = __floats2half2_rn(v2, v3);
            } else {
                *(float2*)(Cf + (size_t)row * N + col)       = make_float2(v0, v1);
                *(float2*)(Cf + (size_t)(row + 8) * N + col) = make_float2(v2, v3);
            }
        }
        if (SCORE) {
            sc0 += __shfl_xor_sync(0xffffffffu, sc0, 1);
            sc0 += __shfl_xor_sync(0xffffffffu, sc0, 2);
            sc1 += __shfl_xor_sync(0xffffffffu, sc1, 1);
            sc1 += __shfl_xor_sync(0xffffffffu, sc1, 2);
            if ((lid & 3) == 0) {
                int tok0 = row, tok1 = row + 8;        // tok = t*NB + b
                int t0_ = tok0 >> 8, b0_ = tok0 & 255;
                int t1_ = tok1 >> 8, b1_ = tok1 & 255;
                float* sp0 = sbuf + (shead * TT + t0_) * NB + b0_;
                float* sp1 = sbuf + (shead * TT + t1_) * NB + b1_;
                if (SCORE == 1) { *sp0 = sc0; *sp1 = sc1; }
                else           { atomicAdd(sp0, sc0); atomicAdd(sp1, sc1); }
            }
        }
    }
}

// ---------------------------------------------------------------------------
// msg tensor-core kernel with FUSED softmax: per (head, t) block covering the
// FULL 256-token batch row. 256 threads (8 warps x 32 token rows). Softmax
// over the 256-score row computed once per block. MMA/epilogue per-element
// math identical to the 128-token version.
// ---------------------------------------------------------------------------
__global__ __launch_bounds__(256)
void msg_mma_kernel(const __half* __restrict__ mwh,
                    const float* __restrict__ mb,
                    const __half* __restrict__ s_h,
                    const float* __restrict__ sbuf) {
    __shared__ __align__(16) __half prodS[256 * 64];   // 32 KB
    __shared__ __align__(16) __half mwS[64 * 64];      //  8 KB
    __shared__ float wtsS[256];
    __shared__ float mbS[64];
    __shared__ float redm[8], reds[8];

    const int h  = blockIdx.y;
    const int t  = blockIdx.x;            // one full batch row per block
    const int p0 = t * NB;                // rows p0..p0+255
    const int tid = threadIdx.x;
    const int wid = tid >> 5, lid = tid & 31;

    if (tid < 64) mbS[tid] = mb[h * 64 + tid];

    {   // mw tile via cp.async (64 rows x 128B, swizzled): 512 chunks
        uint32_t base = smem_u32(mwS);
        #pragma unroll
        for (int it = 0; it < 2; it++) {
            int q = tid + it * 256;
            int r = q >> 3, c = q & 7;
            uint32_t off = (uint32_t)(r * 128 + ((c ^ (r & 7)) << 4));
            cp_async16(base + off, mwh + (size_t)(h * 64 + r) * 64 + c * 8);
        }
        CP_COMMIT();
    }

    {   // fused softmax over the full 256-score row (h, t)
        const float* srow = sbuf + ((size_t)h * TT + t) * NB;
        float v = srow[tid];
        float mx = v;
        #pragma unroll
        for (int o = 16; o; o >>= 1) mx = fmaxf(mx, __shfl_xor_sync(0xffffffffu, mx, o));
        if (lid == 0) redm[wid] = mx;
        __syncthreads();
        mx = fmaxf(fmaxf(fmaxf(redm[0], redm[1]), fmaxf(redm[2], redm[3])),
                   fmaxf(fmaxf(redm[4], redm[5]), fmaxf(redm[6], redm[7])));
        float e = __expf(v - mx);
        float ss = e;
        #pragma unroll
        for (int o = 16; o; o >>= 1) ss += __shfl_xor_sync(0xffffffffu, ss, o);
        if (lid == 0) reds[wid] = ss;
        __syncthreads();
        ss = ((reds[0] + reds[1]) + (reds[2] + reds[3]))
           + ((reds[4] + reds[5]) + (reds[6] + reds[7]));
        wtsS[tid] = e / ss;
    }

    {   // prod tile: s*t on load (coalesced 16B), swizzled store; 2048 chunks
        #pragma unroll
        for (int it = 0; it < 8; it++) {
            int q = tid + it * 256;
            int r = q >> 3, c = q & 7;
            size_t gidx = (size_t)(p0 + r) * ND + h * NSUB + c * 8;
            uint4 sr = *(const uint4*)(s_h + gidx);
            uint4 tr = *(const uint4*)(g_t_h + gidx);
            __half2 a0 = __hmul2(*(__half2*)&sr.x, *(__half2*)&tr.x);
            __half2 a1 = __hmul2(*(__half2*)&sr.y, *(__half2*)&tr.y);
            __half2 a2 = __hmul2(*(__half2*)&sr.z, *(__half2*)&tr.z);
            __half2 a3 = __hmul2(*(__half2*)&sr.w, *(__half2*)&tr.w);
            uint4 p4;
            p4.x = *(uint32_t*)&a0; p4.y = *(uint32_t*)&a1;
            p4.z = *(uint32_t*)&a2; p4.w = *(uint32_t*)&a3;
            uint32_t off = (uint32_t)(r * 128 + ((c ^ (r & 7)) << 4));
            *(uint4*)((char*)prodS + off) = p4;
        }
    }
    CP_WAIT0();
    __syncthreads();

    const int sub = lid >> 3, wi = lid & 7;
    const int csel = sub >> 1;
    const int arow = wid * 32 + (sub & 1) * 8 + wi;   // warp owns 32 token rows
    const int brow = (sub & 1) * 8 + wi;
    const int axor = arow & 7, bxor = brow & 7;
    const uint32_t aB = smem_u32(prodS), bB = smem_u32(mwS);

    float acc[2][8][4] = {};
    #pragma unroll
    for (int ks = 0; ks < 4; ks++) {
        uint32_t af[2][4], bf[4][4];
        #pragma unroll
        for (int mt = 0; mt < 2; mt++)
            ldsm_x4(af[mt], aB + (uint32_t)((arow + mt * 16) * 128)
                               + (uint32_t)((((ks << 1) + csel) ^ axor) << 4));
        #pragma unroll
        for (int np = 0; np < 4; np++)
            ldsm_x4(bf[np], bB + (uint32_t)((brow + np * 16) * 128)
                               + (uint32_t)((((ks << 1) + csel) ^ bxor) << 4));
        #pragma unroll
        for (int mt = 0; mt < 2; mt++)
            #pragma unroll
            for (int nt = 0; nt < 8; nt++)
                mma16816(acc[mt][nt], af[mt],
                         bf[nt >> 1][nt & 1], bf[nt >> 1][(nt & 1) + 2]);
    }

    #pragma unroll
    for (int mt = 0; mt < 2; mt++) {
        int rowl = wid * 32 + mt * 16 + (lid >> 2);
        float wt0 = wtsS[rowl], wt1 = wtsS[rowl + 8];
        size_t ob0 = (size_t)(p0 + rowl) * ND + h * NSUB;
        size_t ob1 = (size_t)(p0 + rowl + 8) * ND + h * NSUB;
        #pragma unroll
        for (int nt = 0; nt < 8; nt++) {
            int u = nt * 8 + (lid & 3) * 2;
            float m0 = acc[mt][nt][0] + mbS[u], m1 = acc[mt][nt][1] + mbS[u + 1];
            float m2 = acc[mt][nt][2] + mbS[u], m3 = acc[mt][nt][3] + mbS[u + 1];
            float v0 = fmaxf(wt0 * m0, 0.f), v1 = fmaxf(wt0 * m1, 0.f);
            float v2 = fmaxf(wt1 * m2, 0.f), v3 = fmaxf(wt1 * m3, 0.f);
            *(__half2*)(g_wm_h + ob0 + u) = __floats2half2_rn(v0, v1);
            *(__half2*)(g_wm_h + ob1 + u) = __floats2half2_rn(v2, v3);
        }
    }
}

// ---------------------------------------------------------------------------
__global__ __launch_bounds__(256)
void f32_to_f16_kernel(const float4* __restrict__ in, __half2* __restrict__ out, int n4) {
    for (int i = blockIdx.x * 256 + threadIdx.x; i < n4; i += gridDim.x * 256) {
        float4 v = in[i];
        out[2 * i]     = __floats2half2_rn(v.x, v.y);
        out[2 * i + 1] = __floats2half2_rn(v.z, v.w);
    }
}

// ---------------------------------------------------------------------------
// Warp-per-token LayerNorms. 8 warps/block. Rows p (layout-agnostic).
// ---------------------------------------------------------------------------
__global__ __launch_bounds__(256)
void ln1_kernel(const float* __restrict__ gam, const float* __restrict__ bet) {
    const int tok = blockIdx.x * 8 + (threadIdx.x >> 5);
    const int l = threadIdx.x & 31;
    const float4* a = (const float4*)(g_agg + (size_t)tok * ND);
    float4 v[4];
    float s = 0.f;
    #pragma unroll
    for (int k = 0; k < 4; k++) {
        v[k] = a[l + 32 * k];
        s += (v[k].x + v[k].y) + (v[k].z + v[k].w);
    }
    #pragma unroll
    for (int o = 16; o; o >>= 1) s += __shfl_xor_sync(0xffffffffu, s, o);
    const float mean = s * (1.0f / ND);
    float q = 0.f;
    #pragma unroll
    for (int k = 0; k < 4; k++) {
        v[k].x -= mean; v[k].y -= mean; v[k].z -= mean; v[k].w -= mean;
        q += (v[k].x * v[k].x + v[k].y * v[k].y) + (v[k].z * v[k].z + v[k].w * v[k].w);
    }
    #pragma unroll
    for (int o = 16; o; o >>= 1) q += __shfl_xor_sync(0xffffffffu, q, o);
    const float rstd = rsqrtf(q * (1.0f / ND) + 1e-5f);
    uint2* xr = (uint2*)(g_x_h + (size_t)tok * ND);
    #pragma unroll
    for (int k = 0; k < 4; k++) {
        int idx = l + 32 * k;
        float4 gg = *(const float4*)(gam + idx * 4);
        float4 bb = *(const float4*)(bet + idx * 4);
        __half2 h0 = __floats2half2_rn(v[k].x * rstd * gg.x + bb.x,
                                       v[k].y * rstd * gg.y + bb.y);
        __half2 h1 = __floats2half2_rn(v[k].z * rstd * gg.z + bb.z,
                                       v[k].w * rstd * gg.w + bb.w);
        uint2 u; u.x = *(uint32_t*)&h0; u.y = *(uint32_t*)&h1;
        xr[idx] = u;
    }
}

__global__ __launch_bounds__(256)
void ln2_kernel(const float* __restrict__ gam, const float* __restrict__ bet,
                float* __restrict__ out, int mode) {
    const int p = blockIdx.x * 8 + (threadIdx.x >> 5);
    const int l = threadIdx.x & 31;
    const float4* a = (const float4*)(g_y + (size_t)p * ND);
    float4 v[4];
    float s = 0.f;
    #pragma unroll
    for (int k = 0; k < 4; k++) {
        v[k] = a[l + 32 * k];
        s += (v[k].x + v[k].y) + (v[k].z + v[k].w);
    }
    #pragma unroll
    for (int o = 16; o; o >>= 1) s += __shfl_xor_sync(0xffffffffu, s, o);
    const float mean = s * (1.0f / ND);
    float q = 0.f;
    #pragma unroll
    for (int k = 0; k < 4; k++) {
        v[k].x -= mean; v[k].y -= mean; v[k].z -= mean; v[k].w -= mean;
        q += (v[k].x * v[k].x + v[k].y * v[k].y) + (v[k].z * v[k].z + v[k].w * v[k].w);
    }
    #pragma unroll
    for (int o = 16; o; o >>= 1) q += __shfl_xor_sync(0xffffffffu, q, o);
    const float rstd = rsqrtf(q * (1.0f / ND) + 1e-5f);
    const size_t obase = (size_t)p * ND;
    float4* orow = (float4*)(out + obase);
    uint2*  hrow = (uint2*)(g_src_h + obase);
    #pragma unroll
    for (int k = 0; k < 4; k++) {
        int idx = l + 32 * k;
        float4 gg = *(const float4*)(gam + idx * 4);
        float4 bb = *(const float4*)(bet + idx * 4);
        float4 o4;
        o4.x = v[k].x * rstd * gg.x + bb.x;
        o4.y = v[k].y * rstd * gg.y + bb.y;
        o4.z = v[k].z * rstd * gg.z + bb.z;
        o4.w = v[k].w * rstd * gg.w + bb.w;
        if (mode == 0) {
            orow[idx] = o4;
        } else {
            __half2 h0 = __floats2half2_rn(o4.x, o4.y);
            __half2 h1 = __floats2half2_rn(o4.z, o4.w);
            uint2 u; u.x = *(uint32_t*)&h0; u.y = *(uint32_t*)&h1;
            hrow[idx] = u;
        }
    }
}

// ---------------------------------------------------------------------------
extern "C" void kernel_launch(void* const* d_in, const int* in_sizes, int n_in,
                              void* d_out, int out_size) {
    const float* in_src  = (const float*)d_in[0];
    const float* in_srcc = (const float*)d_in[1];
    const float* w_sp = (const float*)d_in[2];
    const float* b_sp = (const float*)d_in[3];
    const float* w_tp = (const float*)d_in[4];
    const float* b_tp = (const float*)d_in[5];
    const float* w_at = (const float*)d_in[6];
    const float* w_mg = (const float*)d_in[8];
    const float* b_mg = (const float*)d_in[9];
    const float* w_ag = (const float*)d_in[10];
    const float* b_ag = (const float*)d_in[11];
    const float* w_l1 = (const float*)d_in[12];
    const float* b_l1 = (const float*)d_in[13];
    const float* w_l2 = (const float*)d_in[14];
    const float* b_l2 = (const float*)d_in[15];
    const float* g_n1 = (const float*)d_in[16];
    const float* bb_n1 = (const float*)d_in[17];
    const float* g_n2 = (const float*)d_in[18];
    const float* bb_n2 = (const float*)d_in[19];

    float *p_agg, *p_y, *p_scores;
    __half *p_s_h, *p_t_h, *p_wm_h, *p_x_h, *p_h1_h, *p_src_h, *p_srcc_h, *p_src0_h;
    __half *p_wsp, *p_wtp, *p_wag, *p_wl1, *p_wl2, *p_wmg;
    cudaGetSymbolAddress((void**)&p_s_h,    g_s_h);
    cudaGetSymbolAddress((void**)&p_t_h,    g_t_h);
    cudaGetSymbolAddress((void**)&p_scores, g_scores);
    cudaGetSymbolAddress((void**)&p_agg,    g_agg);
    cudaGetSymbolAddress((void**)&p_y,      g_y);
    cudaGetSymbolAddress((void**)&p_wm_h,   g_wm_h);
    cudaGetSymbolAddress((void**)&p_x_h,    g_x_h);
    cudaGetSymbolAddress((void**)&p_h1_h,   g_h1_h);
    cudaGetSymbolAddress((void**)&p_src_h,  g_src_h);
    cudaGetSymbolAddress((void**)&p_srcc_h, g_srcc_h);
    cudaGetSymbolAddress((void**)&p_src0_h, g_src0_h);
    cudaGetSymbolAddress((void**)&p_wsp,    g_wsp_h);
    cudaGetSymbolAddress((void**)&p_wtp,    g_wtp_h);
    cudaGetSymbolAddress((void**)&p_wag,    g_wag_h);
    cudaGetSymbolAddress((void**)&p_wl1,    g_wl1_h);
    cudaGetSymbolAddress((void**)&p_wl2,    g_wl2_h);
    cudaGetSymbolAddress((void**)&p_wmg,    g_wmg_h);

    cudaFuncSetAttribute(tc_gemm<1, 1, 0, 1>, cudaFuncAttributeMaxDynamicSharedMemorySize, DYN_SMEM);
    cudaFuncSetAttribute(tc_gemm<1, 1, 0, 2>, cudaFuncAttributeMaxDynamicSharedMemorySize, DYN_SMEM);
    cudaFuncSetAttribute(tc_gemm<0, 0, 1, 0>, cudaFuncAttributeMaxDynamicSharedMemorySize, DYN_SMEM);
    cudaFuncSetAttribute(tc_gemm<1, 1, 0, 0>, cudaFuncAttributeMaxDynamicSharedMemorySize, DYN_SMEM);
    cudaFuncSetAttribute(tc_gemm<0, 0, 3, 0>, cudaFuncAttributeMaxDynamicSharedMemorySize, DYN_SMEM);

    // one-time fp16 conversions (8 separate launches — proven fastest)
    f32_to_f16_kernel<<<2048, 256>>>((const float4*)in_srcc, (__half2*)p_srcc_h, NTOK * ND / 4);
    f32_to_f16_kernel<<<2048, 256>>>((const float4*)in_src,  (__half2*)p_src0_h, NTOK * ND / 4);
    f32_to_f16_kernel<<<2048, 256>>>((const float4*)w_sp, (__half2*)p_wsp, NL * ND * ND / 4);
    f32_to_f16_kernel<<<2048, 256>>>((const float4*)w_tp, (__half2*)p_wtp, NL * ND * ND / 4);
    f32_to_f16_kernel<<<2048, 256>>>((const float4*)w_ag, (__half2*)p_wag, NL * ND * ND / 4);
    f32_to_f16_kernel<<<2048, 256>>>((const float4*)w_l1, (__half2*)p_wl1, NL * NDFF * ND / 4);
    f32_to_f16_kernel<<<2048, 256>>>((const float4*)w_l2, (__half2*)p_wl2, NL * ND * NDFF / 4);
    f32_to_f16_kernel<<<192, 256>>>((const float4*)w_mg, (__half2*)p_wmg,
                                    NL * NH * NSUB * NSUB / 4);

    // hoisted: ALL layers' s = relu(srcc @ sw_l^T + sb_l) + s-part scores
    tc_gemm<1, 1, 0, 1><<<dim3(ND / BN, NTOK / BM, NL), 128, DYN_SMEM>>>(
        p_srcc_h, p_wsp, b_sp, nullptr, p_s_h, nullptr, w_at, p_scores, ND, ND);

    const dim3 gemm_dd(ND / BN, NTOK / BM);
    for (int l = 0; l < NL; l++) {
        const __half* srcA = (l == 0) ? p_src0_h : p_src_h;
        const float*  awl  = w_at + (size_t)l * NH * 2 * NSUB;
        float* sbl = p_scores + (size_t)l * NH * TT * NB;

        // t = relu(src @ tw^T + tb) [fp16 out] + ATOMIC-ADD t-part scores
        tc_gemm<1, 1, 0, 2><<<gemm_dd, 128, DYN_SMEM>>>(
            srcA, p_wtp + (size_t)l * ND * ND, b_tp + l * ND,
            nullptr, p_t_h, nullptr, awl, sbl, ND, ND);
        // weighted message via tensor cores, softmax fused (full row per block)
        msg_mma_kernel<<<dim3(TT, NH), 256>>>(
            p_wmg + (size_t)l * NH * NSUB * NSUB, b_mg + l * NH * NSUB,
            p_s_h + (size_t)l * NTOK * ND, sbl);
        // agg = wm @ gw^T + gb + src  [fp32 out, same-layout residual fused]
        if (l == 0)
            tc_gemm<0, 0, 1, 0><<<gemm_dd, 128, DYN_SMEM>>>(
                p_wm_h, p_wag + (size_t)l * ND * ND, b_ag + l * ND,
                p_agg, nullptr, in_src, nullptr, nullptr, ND, ND);
        else
            tc_gemm<0, 0, 3, 0><<<gemm_dd, 128, DYN_SMEM>>>(
                p_wm_h, p_wag + (size_t)l * ND * ND, b_ag + l * ND,
                p_agg, nullptr, p_src_h, nullptr, nullptr, ND, ND);
        // x = LN(agg')  [fp16 only]
        ln1_kernel<<<NTOK / 8, 256>>>(g_n1 + l * ND, bb_n1 + l * ND);
        // h1 = relu(x @ w1^T + b1)  [fp16 out]
        tc_gemm<1, 1, 0, 0><<<dim3(NDFF / BN, NTOK / BM), 128, DYN_SMEM>>>(
            p_x_h, p_wl1 + (size_t)l * NDFF * ND, b_l1 + l * NDFF,
            nullptr, p_h1_h, nullptr, nullptr, nullptr, ND, NDFF);
        // y = h1 @ w2^T + b2 + x(fp16)  [fp32 out, fp16 residual fused]
        tc_gemm<0, 0, 3, 0><<<gemm_dd, 128, DYN_SMEM>>>(
            p_h1_h, p_wl2 + (size_t)l * ND * NDFF, b_l2 + l * ND,
            p_y, nullptr, p_x_h, nullptr, nullptr, NDFF, ND);
        // out = LN(y') row p: last layer fp32 d_out, else fp16 g_src_h
        ln2_kernel<<<NTOK / 8, 256>>>(g_n2 + l * ND, bb_n2 + l * ND,
                                      (float*)d_out, (l == NL - 1) ? 0 : 1);
    }
}